// round 1
// baseline (speedup 1.0000x reference)
#include <cuda_runtime.h>
#include <cstddef>

#define D_MODEL 1024
#define NHEAD   16
#define DK      64
#define BATCH   2
#define SEQ     2048
#define M_TOT   (BATCH * SEQ)   // 4096

// Scratch (allocation-free: __device__ globals)
__device__ float g_Q[(size_t)M_TOT * D_MODEL];
__device__ float g_K[(size_t)M_TOT * D_MODEL];
__device__ float g_V[(size_t)M_TOT * D_MODEL];
__device__ float g_C[(size_t)M_TOT * D_MODEL];

// ---------------------------------------------------------------------------
// Y[M=4096, N=1024] = X[4096,1024] @ W[1024,1024]^T + bias  (torch Linear)
// 64x64 tile, BK=16, 256 threads, 4x4 per thread, smem staged transposed.
// ---------------------------------------------------------------------------
__global__ __launch_bounds__(256) void gemm_bias_kernel(
    const float* __restrict__ X, const float* __restrict__ W,
    const float* __restrict__ bias, float* __restrict__ Y)
{
    __shared__ float As[16][64];
    __shared__ float Bs[16][64];

    const int t  = threadIdx.x;
    const int tx = t & 15;        // 0..15 -> output col group
    const int ty = t >> 4;        // 0..15 -> output row group
    const int m0 = blockIdx.y << 6;
    const int n0 = blockIdx.x << 6;

    const int lr = t >> 2;        // 0..63 row within tile (load)
    const int lk = (t & 3) << 2;  // 0,4,8,12 k offset (load)

    const float* Xp = X + (size_t)(m0 + lr) * D_MODEL + lk;
    const float* Wp = W + (size_t)(n0 + lr) * D_MODEL + lk;

    float acc[4][4] = {};

    for (int k0 = 0; k0 < D_MODEL; k0 += 16) {
        float4 av = *(const float4*)(Xp + k0);
        float4 bv = *(const float4*)(Wp + k0);
        __syncthreads();
        As[lk + 0][lr] = av.x; As[lk + 1][lr] = av.y;
        As[lk + 2][lr] = av.z; As[lk + 3][lr] = av.w;
        Bs[lk + 0][lr] = bv.x; Bs[lk + 1][lr] = bv.y;
        Bs[lk + 2][lr] = bv.z; Bs[lk + 3][lr] = bv.w;
        __syncthreads();
#pragma unroll
        for (int kk = 0; kk < 16; kk++) {
            float4 a = *(const float4*)&As[kk][ty << 2];
            float4 b = *(const float4*)&Bs[kk][tx << 2];
            acc[0][0] += a.x * b.x; acc[0][1] += a.x * b.y; acc[0][2] += a.x * b.z; acc[0][3] += a.x * b.w;
            acc[1][0] += a.y * b.x; acc[1][1] += a.y * b.y; acc[1][2] += a.y * b.z; acc[1][3] += a.y * b.w;
            acc[2][0] += a.z * b.x; acc[2][1] += a.z * b.y; acc[2][2] += a.z * b.z; acc[2][3] += a.z * b.w;
            acc[3][0] += a.w * b.x; acc[3][1] += a.w * b.y; acc[3][2] += a.w * b.z; acc[3][3] += a.w * b.w;
        }
    }

    float4 bb = *(const float4*)(bias + n0 + (tx << 2));
#pragma unroll
    for (int i = 0; i < 4; i++) {
        float4 o;
        o.x = acc[i][0] + bb.x; o.y = acc[i][1] + bb.y;
        o.z = acc[i][2] + bb.z; o.w = acc[i][3] + bb.w;
        *(float4*)(Y + (size_t)(m0 + (ty << 2) + i) * D_MODEL + n0 + (tx << 2)) = o;
    }
}

// ---------------------------------------------------------------------------
// Flash-style attention: one block = 64 queries x (head, batch).
// Online softmax; soft mask (score -> -1 where mask==0). Writes context to g_C
// in [B, S, H*DK] layout for the output projection.
// smem (dynamic, 67584 B): Qs[64][64] (dim-major), Ks[64][64] (dim-major),
//                          Vs[64][68] (key-major), Ps[64][68] (row-major)
// ---------------------------------------------------------------------------
__global__ __launch_bounds__(256) void attn_kernel(const int* __restrict__ mask)
{
    extern __shared__ float sm[];
    float (*Qs)[64] = (float(*)[64])(sm);
    float (*Ks)[64] = (float(*)[64])(sm + 64 * 64);
    float (*Vs)[68] = (float(*)[68])(sm + 2 * 64 * 64);
    float (*Ps)[68] = (float(*)[68])(sm + 2 * 64 * 64 + 64 * 68);

    const int t  = threadIdx.x;
    const int tx = t & 15;
    const int ty = t >> 4;
    const int b  = blockIdx.z;
    const int h  = blockIdx.y;
    const int q0 = blockIdx.x << 6;
    const int lr = t >> 2;        // 0..63 (row/key to load)
    const int qd = t & 3;

    const float* Qg    = g_Q + ((size_t)(b * SEQ + q0 + lr)) * D_MODEL + h * DK;
    const float* Kbase = g_K + ((size_t)b * SEQ) * D_MODEL + h * DK;
    const float* Vbase = g_V + ((size_t)b * SEQ) * D_MODEL + h * DK;

    // Load Q tile (transposed: Qs[dim][row])
#pragma unroll
    for (int u = 0; u < 4; u++) {
        int d = (qd + 4 * u) << 2;
        float4 v = *(const float4*)(Qg + d);
        Qs[d + 0][lr] = v.x; Qs[d + 1][lr] = v.y;
        Qs[d + 2][lr] = v.z; Qs[d + 3][lr] = v.w;
    }

    float acc[4][4] = {};
    float mrow[4], lsum[4];
#pragma unroll
    for (int i = 0; i < 4; i++) { mrow[i] = -1e30f; lsum[i] = 0.0f; }

    const int qg0 = q0 + (ty << 2);

    for (int kt = 0; kt < SEQ / 64; kt++) {
        const int k0 = kt << 6;
        __syncthreads();   // protect Ks/Vs/Ps from previous iteration readers

        const float* Kg = Kbase + (size_t)(k0 + lr) * D_MODEL;
        const float* Vg = Vbase + (size_t)(k0 + lr) * D_MODEL;
#pragma unroll
        for (int u = 0; u < 4; u++) {
            int d = (qd + 4 * u) << 2;
            float4 kv = *(const float4*)(Kg + d);
            Ks[d + 0][lr] = kv.x; Ks[d + 1][lr] = kv.y;
            Ks[d + 2][lr] = kv.z; Ks[d + 3][lr] = kv.w;
            float4 vv = *(const float4*)(Vg + d);
            *(float4*)&Vs[lr][d] = vv;
        }
        __syncthreads();

        // Scores: s[4][4] = Q(rows ty*4..) . K(cols tx*4..)
        float s[4][4] = {};
#pragma unroll 8
        for (int kk = 0; kk < 64; kk++) {
            float4 a  = *(const float4*)&Qs[kk][ty << 2];
            float4 bb = *(const float4*)&Ks[kk][tx << 2];
            s[0][0] += a.x * bb.x; s[0][1] += a.x * bb.y; s[0][2] += a.x * bb.z; s[0][3] += a.x * bb.w;
            s[1][0] += a.y * bb.x; s[1][1] += a.y * bb.y; s[1][2] += a.y * bb.z; s[1][3] += a.y * bb.w;
            s[2][0] += a.z * bb.x; s[2][1] += a.z * bb.y; s[2][2] += a.z * bb.z; s[2][3] += a.z * bb.w;
            s[3][0] += a.w * bb.x; s[3][1] += a.w * bb.y; s[3][2] += a.w * bb.z; s[3][3] += a.w * bb.w;
        }

        // Scale + soft mask (mask==0 -> -1.0, else score/8)
#pragma unroll
        for (int i = 0; i < 4; i++) {
            int4 mk = *(const int4*)&mask[(size_t)(qg0 + i) * SEQ + k0 + (tx << 2)];
            s[i][0] = mk.x ? s[i][0] * 0.125f : -1.0f;
            s[i][1] = mk.y ? s[i][1] * 0.125f : -1.0f;
            s[i][2] = mk.z ? s[i][2] * 0.125f : -1.0f;
            s[i][3] = mk.w ? s[i][3] * 0.125f : -1.0f;
        }

        // Online softmax per row (16-lane row groups; xor shuffles stay in-group)
#pragma unroll
        for (int i = 0; i < 4; i++) {
            float tm = fmaxf(fmaxf(s[i][0], s[i][1]), fmaxf(s[i][2], s[i][3]));
            tm = fmaxf(tm, __shfl_xor_sync(0xffffffffu, tm, 1));
            tm = fmaxf(tm, __shfl_xor_sync(0xffffffffu, tm, 2));
            tm = fmaxf(tm, __shfl_xor_sync(0xffffffffu, tm, 4));
            tm = fmaxf(tm, __shfl_xor_sync(0xffffffffu, tm, 8));
            float mn = fmaxf(mrow[i], tm);
            float p0 = __expf(s[i][0] - mn);
            float p1 = __expf(s[i][1] - mn);
            float p2 = __expf(s[i][2] - mn);
            float p3 = __expf(s[i][3] - mn);
            float rs = (p0 + p1) + (p2 + p3);
            rs += __shfl_xor_sync(0xffffffffu, rs, 1);
            rs += __shfl_xor_sync(0xffffffffu, rs, 2);
            rs += __shfl_xor_sync(0xffffffffu, rs, 4);
            rs += __shfl_xor_sync(0xffffffffu, rs, 8);
            float alpha = __expf(mrow[i] - mn);
            lsum[i] = lsum[i] * alpha + rs;
            mrow[i] = mn;
            acc[i][0] *= alpha; acc[i][1] *= alpha;
            acc[i][2] *= alpha; acc[i][3] *= alpha;
            *(float4*)&Ps[(ty << 2) + i][tx << 2] = make_float4(p0, p1, p2, p3);
        }
        __syncthreads();

        // acc += P . V
#pragma unroll 4
        for (int kk = 0; kk < 64; kk += 4) {
            float4 p0 = *(const float4*)&Ps[(ty << 2) + 0][kk];
            float4 p1 = *(const float4*)&Ps[(ty << 2) + 1][kk];
            float4 p2 = *(const float4*)&Ps[(ty << 2) + 2][kk];
            float4 p3 = *(const float4*)&Ps[(ty << 2) + 3][kk];
            float4 v0 = *(const float4*)&Vs[kk + 0][tx << 2];
            float4 v1 = *(const float4*)&Vs[kk + 1][tx << 2];
            float4 v2 = *(const float4*)&Vs[kk + 2][tx << 2];
            float4 v3 = *(const float4*)&Vs[kk + 3][tx << 2];
            acc[0][0] += p0.x * v0.x + p0.y * v1.x + p0.z * v2.x + p0.w * v3.x;
            acc[0][1] += p0.x * v0.y + p0.y * v1.y + p0.z * v2.y + p0.w * v3.y;
            acc[0][2] += p0.x * v0.z + p0.y * v1.z + p0.z * v2.z + p0.w * v3.z;
            acc[0][3] += p0.x * v0.w + p0.y * v1.w + p0.z * v2.w + p0.w * v3.w;
            acc[1][0] += p1.x * v0.x + p1.y * v1.x + p1.z * v2.x + p1.w * v3.x;
            acc[1][1] += p1.x * v0.y + p1.y * v1.y + p1.z * v2.y + p1.w * v3.y;
            acc[1][2] += p1.x * v0.z + p1.y * v1.z + p1.z * v2.z + p1.w * v3.z;
            acc[1][3] += p1.x * v0.w + p1.y * v1.w + p1.z * v2.w + p1.w * v3.w;
            acc[2][0] += p2.x * v0.x + p2.y * v1.x + p2.z * v2.x + p2.w * v3.x;
            acc[2][1] += p2.x * v0.y + p2.y * v1.y + p2.z * v2.y + p2.w * v3.y;
            acc[2][2] += p2.x * v0.z + p2.y * v1.z + p2.z * v2.z + p2.w * v3.z;
            acc[2][3] += p2.x * v0.w + p2.y * v1.w + p2.z * v2.w + p2.w * v3.w;
            acc[3][0] += p3.x * v0.x + p3.y * v1.x + p3.z * v2.x + p3.w * v3.x;
            acc[3][1] += p3.x * v0.y + p3.y * v1.y + p3.z * v2.y + p3.w * v3.y;
            acc[3][2] += p3.x * v0.z + p3.y * v1.z + p3.z * v2.z + p3.w * v3.z;
            acc[3][3] += p3.x * v0.w + p3.y * v1.w + p3.z * v2.w + p3.w * v3.w;
        }
    }

    // Normalize and write context (layout [B,S,H*DK])
    float* Cg = g_C + ((size_t)(b * SEQ + qg0)) * D_MODEL + h * DK + (tx << 2);
#pragma unroll
    for (int i = 0; i < 4; i++) {
        float inv = 1.0f / lsum[i];
        *(float4*)(Cg + (size_t)i * D_MODEL) =
            make_float4(acc[i][0] * inv, acc[i][1] * inv, acc[i][2] * inv, acc[i][3] * inv);
    }
}

// ---------------------------------------------------------------------------
extern "C" void kernel_launch(void* const* d_in, const int* in_sizes, int n_in,
                              void* d_out, int out_size)
{
    const float* q    = (const float*)d_in[0];
    const float* k    = (const float*)d_in[1];
    const float* v    = (const float*)d_in[2];
    const int*   mask = (const int*)  d_in[3];
    const float* wq   = (const float*)d_in[4];
    const float* bq   = (const float*)d_in[5];
    const float* wk   = (const float*)d_in[6];
    const float* bk   = (const float*)d_in[7];
    const float* wv   = (const float*)d_in[8];
    const float* bv   = (const float*)d_in[9];
    const float* wo   = (const float*)d_in[10];
    const float* bo   = (const float*)d_in[11];
    float* out = (float*)d_out;

    float *gQ, *gK, *gV, *gC;
    cudaGetSymbolAddress((void**)&gQ, g_Q);
    cudaGetSymbolAddress((void**)&gK, g_K);
    cudaGetSymbolAddress((void**)&gV, g_V);
    cudaGetSymbolAddress((void**)&gC, g_C);

    const int attn_smem = (2 * 64 * 64 + 2 * 64 * 68) * (int)sizeof(float); // 67584
    cudaFuncSetAttribute(attn_kernel, cudaFuncAttributeMaxDynamicSharedMemorySize, attn_smem);

    dim3 gemm_grid(D_MODEL / 64, M_TOT / 64);   // (16, 64)
    gemm_bias_kernel<<<gemm_grid, 256>>>(q, wq, bq, gQ);
    gemm_bias_kernel<<<gemm_grid, 256>>>(k, wk, bk, gK);
    gemm_bias_kernel<<<gemm_grid, 256>>>(v, wv, bv, gV);

    dim3 attn_grid(SEQ / 64, NHEAD, BATCH);     // (32, 16, 2)
    attn_kernel<<<attn_grid, 256, attn_smem>>>(mask);

    gemm_bias_kernel<<<gemm_grid, 256>>>(gC, wo, bo, out);
}

// round 3
// speedup vs baseline: 1.5152x; 1.5152x over previous
#include <cuda_runtime.h>
#include <cuda_bf16.h>
#include <cstdint>
#include <cstddef>

#define D_MODEL 1024
#define NHEAD   16
#define DK      64
#define BATCH   2
#define SEQ     2048
#define M_TOT   (BATCH * SEQ)   // 4096

// Scratch (allocation-free: __device__ globals)
__device__ float g_Q[(size_t)M_TOT * D_MODEL];
__device__ float g_K[(size_t)M_TOT * D_MODEL];
__device__ float g_V[(size_t)M_TOT * D_MODEL];
__device__ float g_C[(size_t)M_TOT * D_MODEL];

// ===========================================================================
// Helpers (baseline PTX ISA only — no sm_103a-specific features)
// ===========================================================================
__device__ __forceinline__ uint32_t smem_u32(const void* p) {
    uint32_t a;
    asm("{ .reg .u64 t; cvta.to.shared.u64 t, %1; cvt.u32.u64 %0, t; }"
        : "=r"(a) : "l"(p));
    return a;
}

#define LDM4(r, addr) \
    asm volatile("ldmatrix.sync.aligned.m8n8.x4.shared.b16 {%0,%1,%2,%3}, [%4];" \
        : "=r"((r)[0]), "=r"((r)[1]), "=r"((r)[2]), "=r"((r)[3]) : "r"(addr))

#define MMA_BF16(d, a, b0, b1) \
    asm volatile("mma.sync.aligned.m16n8k16.row.col.f32.bf16.bf16.f32 " \
        "{%0,%1,%2,%3}, {%4,%5,%6,%7}, {%8,%9}, {%0,%1,%2,%3};" \
        : "+f"((d)[0]), "+f"((d)[1]), "+f"((d)[2]), "+f"((d)[3]) \
        : "r"((a)[0]), "r"((a)[1]), "r"((a)[2]), "r"((a)[3]), "r"(b0), "r"(b1))

// fp32 -> (hi bf16, lo bf16) split, 4 elements packed into two uint2
__device__ __forceinline__ void cvt4_split(float4 f, uint2& hi, uint2& lo) {
    __nv_bfloat16 h0 = __float2bfloat16_rn(f.x);
    __nv_bfloat16 h1 = __float2bfloat16_rn(f.y);
    __nv_bfloat16 h2 = __float2bfloat16_rn(f.z);
    __nv_bfloat16 h3 = __float2bfloat16_rn(f.w);
    __nv_bfloat16 l0 = __float2bfloat16_rn(f.x - __bfloat162float(h0));
    __nv_bfloat16 l1 = __float2bfloat16_rn(f.y - __bfloat162float(h1));
    __nv_bfloat16 l2 = __float2bfloat16_rn(f.z - __bfloat162float(h2));
    __nv_bfloat16 l3 = __float2bfloat16_rn(f.w - __bfloat162float(h3));
    __nv_bfloat162 p0; p0.x = h0; p0.y = h1;
    __nv_bfloat162 p1; p1.x = h2; p1.y = h3;
    __nv_bfloat162 p2; p2.x = l0; p2.y = l1;
    __nv_bfloat162 p3; p3.x = l2; p3.y = l3;
    hi.x = *(uint32_t*)&p0; hi.y = *(uint32_t*)&p1;
    lo.x = *(uint32_t*)&p2; lo.y = *(uint32_t*)&p3;
}

// ===========================================================================
// Tensor-core GEMM (mma.sync bf16, 2-term split): Y[4096,1024] = X @ W^T + b
// CTA tile 128x128, BK=32, 8 warps (2x4), warp tile 64x32.
// SMEM per buffer: Ahi/Alo/Bhi/Blo, 128 rows x 80B (padded) each = 40960 B.
// Double buffered: 81920 B dynamic smem.
// ===========================================================================
#define RS        80          // padded row stride (bytes) for 32 bf16 = 64 B data
#define TILE_SZ   10240       // 128 * RS
#define BUF_SZ    40960       // 4 tiles
#define GEMM_SMEM 81920

__global__ __launch_bounds__(256) void gemm_mma_kernel(
    const float* __restrict__ X, const float* __restrict__ W,
    const float* __restrict__ bias, float* __restrict__ Y)
{
    extern __shared__ char sm[];
    const uint32_t sb = smem_u32(sm);
    const int t    = threadIdx.x;
    const int lane = t & 31;
    const int wid  = t >> 5;
    const int wm   = (wid & 1) << 6;   // 0 / 64
    const int wn   = (wid >> 1) << 5;  // 0 / 32 / 64 / 96
    const int m0 = blockIdx.y << 7;
    const int n0 = blockIdx.x << 7;

    float4 ra[4], rb[4];

    // ---- global load (K-tile k0) into regs ----
    auto g_load = [&](int k0) {
#pragma unroll
        for (int i = 0; i < 4; i++) {
            const int idx = t + (i << 8);
            const int r = idx >> 3, c = idx & 7;
            ra[i] = *(const float4*)(X + (size_t)(m0 + r) * D_MODEL + k0 + (c << 2));
            rb[i] = *(const float4*)(W + (size_t)(n0 + r) * D_MODEL + k0 + (c << 2));
        }
    };
    // ---- convert + store regs into smem buffer ----
    auto s_store = [&](int base) {
#pragma unroll
        for (int i = 0; i < 4; i++) {
            const int idx = t + (i << 8);
            const int r = idx >> 3, c = idx & 7;
            const int off = r * RS + (c << 3);
            uint2 hi, lo;
            cvt4_split(ra[i], hi, lo);
            *(uint2*)(sm + base + off)           = hi;
            *(uint2*)(sm + base + TILE_SZ + off) = lo;
            cvt4_split(rb[i], hi, lo);
            *(uint2*)(sm + base + 2 * TILE_SZ + off) = hi;
            *(uint2*)(sm + base + 3 * TILE_SZ + off) = lo;
        }
    };

    float acc[4][4][4] = {};

    g_load(0);
    s_store(0);
    __syncthreads();

    for (int kt = 0; kt < D_MODEL / 32; kt++) {       // 32 stages
        if (kt < 31) g_load((kt + 1) << 5);

        const uint32_t buf = sb + (kt & 1) * BUF_SZ;
#pragma unroll
        for (int ks = 0; ks < 2; ks++) {
            const int kb = ks << 5;   // byte offset of 16-bf16 k-step
            uint32_t a_hi[4][4], a_lo[4][4];
            uint32_t b_hi[4][2], b_lo[4][2];
#pragma unroll
            for (int mi = 0; mi < 4; mi++) {
                const uint32_t r = wm + (mi << 4) + (lane & 15);
                const uint32_t ad = buf + r * RS + kb + ((lane >> 4) << 4);
                LDM4(a_hi[mi], ad);
                LDM4(a_lo[mi], ad + TILE_SZ);
            }
#pragma unroll
            for (int p = 0; p < 2; p++) {
                const uint32_t nr = wn + (p << 4) + (lane & 7) + ((lane >> 4) << 3);
                const uint32_t ad = buf + 2 * TILE_SZ + nr * RS + kb + (((lane >> 3) & 1) << 4);
                uint32_t q[4];
                LDM4(q, ad);
                b_hi[2 * p][0] = q[0]; b_hi[2 * p][1] = q[1];
                b_hi[2 * p + 1][0] = q[2]; b_hi[2 * p + 1][1] = q[3];
                LDM4(q, ad + TILE_SZ);
                b_lo[2 * p][0] = q[0]; b_lo[2 * p][1] = q[1];
                b_lo[2 * p + 1][0] = q[2]; b_lo[2 * p + 1][1] = q[3];
            }
#pragma unroll
            for (int mi = 0; mi < 4; mi++)
#pragma unroll
                for (int ni = 0; ni < 4; ni++) {
                    MMA_BF16(acc[mi][ni], a_hi[mi], b_hi[ni][0], b_hi[ni][1]);
                    MMA_BF16(acc[mi][ni], a_hi[mi], b_lo[ni][0], b_lo[ni][1]);
                    MMA_BF16(acc[mi][ni], a_lo[mi], b_hi[ni][0], b_hi[ni][1]);
                }
        }

        if (kt < 31) {
            s_store(((kt + 1) & 1) * BUF_SZ);
            __syncthreads();
        }
    }

    // ---- epilogue: + bias, write fp32 ----
    const int lr4 = lane >> 2;
    const int lc2 = (lane & 3) << 1;
#pragma unroll
    for (int mi = 0; mi < 4; mi++) {
        const int r = m0 + wm + (mi << 4) + lr4;
#pragma unroll
        for (int ni = 0; ni < 4; ni++) {
            const int c = n0 + wn + (ni << 3) + lc2;
            const float bx = bias[c], by = bias[c + 1];
            float2 o0, o1;
            o0.x = acc[mi][ni][0] + bx; o0.y = acc[mi][ni][1] + by;
            o1.x = acc[mi][ni][2] + bx; o1.y = acc[mi][ni][3] + by;
            *(float2*)(Y + (size_t)r * D_MODEL + c)       = o0;
            *(float2*)(Y + (size_t)(r + 8) * D_MODEL + c) = o1;
        }
    }
}

// ---------------------------------------------------------------------------
// Flash-style attention (round-1 proven kernel, unchanged).
// ---------------------------------------------------------------------------
__global__ __launch_bounds__(256) void attn_kernel(const int* __restrict__ mask)
{
    extern __shared__ float smf[];
    float (*Qs)[64] = (float(*)[64])(smf);
    float (*Ks)[64] = (float(*)[64])(smf + 64 * 64);
    float (*Vs)[68] = (float(*)[68])(smf + 2 * 64 * 64);
    float (*Ps)[68] = (float(*)[68])(smf + 2 * 64 * 64 + 64 * 68);

    const int t  = threadIdx.x;
    const int tx = t & 15;
    const int ty = t >> 4;
    const int b  = blockIdx.z;
    const int h  = blockIdx.y;
    const int q0 = blockIdx.x << 6;
    const int lr = t >> 2;
    const int qd = t & 3;

    const float* Qg    = g_Q + ((size_t)(b * SEQ + q0 + lr)) * D_MODEL + h * DK;
    const float* Kbase = g_K + ((size_t)b * SEQ) * D_MODEL + h * DK;
    const float* Vbase = g_V + ((size_t)b * SEQ) * D_MODEL + h * DK;

#pragma unroll
    for (int u = 0; u < 4; u++) {
        int d = (qd + 4 * u) << 2;
        float4 v = *(const float4*)(Qg + d);
        Qs[d + 0][lr] = v.x; Qs[d + 1][lr] = v.y;
        Qs[d + 2][lr] = v.z; Qs[d + 3][lr] = v.w;
    }

    float acc[4][4] = {};
    float mrow[4], lsum[4];
#pragma unroll
    for (int i = 0; i < 4; i++) { mrow[i] = -1e30f; lsum[i] = 0.0f; }

    const int qg0 = q0 + (ty << 2);

    for (int kt = 0; kt < SEQ / 64; kt++) {
        const int k0 = kt << 6;
        __syncthreads();

        const float* Kg = Kbase + (size_t)(k0 + lr) * D_MODEL;
        const float* Vg = Vbase + (size_t)(k0 + lr) * D_MODEL;
#pragma unroll
        for (int u = 0; u < 4; u++) {
            int d = (qd + 4 * u) << 2;
            float4 kv = *(const float4*)(Kg + d);
            Ks[d + 0][lr] = kv.x; Ks[d + 1][lr] = kv.y;
            Ks[d + 2][lr] = kv.z; Ks[d + 3][lr] = kv.w;
            float4 vv = *(const float4*)(Vg + d);
            *(float4*)&Vs[lr][d] = vv;
        }
        __syncthreads();

        float s[4][4] = {};
#pragma unroll 8
        for (int kk = 0; kk < 64; kk++) {
            float4 a  = *(const float4*)&Qs[kk][ty << 2];
            float4 bb = *(const float4*)&Ks[kk][tx << 2];
            s[0][0] += a.x * bb.x; s[0][1] += a.x * bb.y; s[0][2] += a.x * bb.z; s[0][3] += a.x * bb.w;
            s[1][0] += a.y * bb.x; s[1][1] += a.y * bb.y; s[1][2] += a.y * bb.z; s[1][3] += a.y * bb.w;
            s[2][0] += a.z * bb.x; s[2][1] += a.z * bb.y; s[2][2] += a.z * bb.z; s[2][3] += a.z * bb.w;
            s[3][0] += a.w * bb.x; s[3][1] += a.w * bb.y; s[3][2] += a.w * bb.z; s[3][3] += a.w * bb.w;
        }

#pragma unroll
        for (int i = 0; i < 4; i++) {
            int4 mk = *(const int4*)&mask[(size_t)(qg0 + i) * SEQ + k0 + (tx << 2)];
            s[i][0] = mk.x ? s[i][0] * 0.125f : -1.0f;
            s[i][1] = mk.y ? s[i][1] * 0.125f : -1.0f;
            s[i][2] = mk.z ? s[i][2] * 0.125f : -1.0f;
            s[i][3] = mk.w ? s[i][3] * 0.125f : -1.0f;
        }

#pragma unroll
        for (int i = 0; i < 4; i++) {
            float tm = fmaxf(fmaxf(s[i][0], s[i][1]), fmaxf(s[i][2], s[i][3]));
            tm = fmaxf(tm, __shfl_xor_sync(0xffffffffu, tm, 1));
            tm = fmaxf(tm, __shfl_xor_sync(0xffffffffu, tm, 2));
            tm = fmaxf(tm, __shfl_xor_sync(0xffffffffu, tm, 4));
            tm = fmaxf(tm, __shfl_xor_sync(0xffffffffu, tm, 8));
            float mn = fmaxf(mrow[i], tm);
            float p0 = __expf(s[i][0] - mn);
            float p1 = __expf(s[i][1] - mn);
            float p2 = __expf(s[i][2] - mn);
            float p3 = __expf(s[i][3] - mn);
            float rs = (p0 + p1) + (p2 + p3);
            rs += __shfl_xor_sync(0xffffffffu, rs, 1);
            rs += __shfl_xor_sync(0xffffffffu, rs, 2);
            rs += __shfl_xor_sync(0xffffffffu, rs, 4);
            rs += __shfl_xor_sync(0xffffffffu, rs, 8);
            float alpha = __expf(mrow[i] - mn);
            lsum[i] = lsum[i] * alpha + rs;
            mrow[i] = mn;
            acc[i][0] *= alpha; acc[i][1] *= alpha;
            acc[i][2] *= alpha; acc[i][3] *= alpha;
            *(float4*)&Ps[(ty << 2) + i][tx << 2] = make_float4(p0, p1, p2, p3);
        }
        __syncthreads();

#pragma unroll 4
        for (int kk = 0; kk < 64; kk += 4) {
            float4 p0 = *(const float4*)&Ps[(ty << 2) + 0][kk];
            float4 p1 = *(const float4*)&Ps[(ty << 2) + 1][kk];
            float4 p2 = *(const float4*)&Ps[(ty << 2) + 2][kk];
            float4 p3 = *(const float4*)&Ps[(ty << 2) + 3][kk];
            float4 v0 = *(const float4*)&Vs[kk + 0][tx << 2];
            float4 v1 = *(const float4*)&Vs[kk + 1][tx << 2];
            float4 v2 = *(const float4*)&Vs[kk + 2][tx << 2];
            float4 v3 = *(const float4*)&Vs[kk + 3][tx << 2];
            acc[0][0] += p0.x * v0.x + p0.y * v1.x + p0.z * v2.x + p0.w * v3.x;
            acc[0][1] += p0.x * v0.y + p0.y * v1.y + p0.z * v2.y + p0.w * v3.y;
            acc[0][2] += p0.x * v0.z + p0.y * v1.z + p0.z * v2.z + p0.w * v3.z;
            acc[0][3] += p0.x * v0.w + p0.y * v1.w + p0.z * v2.w + p0.w * v3.w;
            acc[1][0] += p1.x * v0.x + p1.y * v1.x + p1.z * v2.x + p1.w * v3.x;
            acc[1][1] += p1.x * v0.y + p1.y * v1.y + p1.z * v2.y + p1.w * v3.y;
            acc[1][2] += p1.x * v0.z + p1.y * v1.z + p1.z * v2.z + p1.w * v3.z;
            acc[1][3] += p1.x * v0.w + p1.y * v1.w + p1.z * v2.w + p1.w * v3.w;
            acc[2][0] += p2.x * v0.x + p2.y * v1.x + p2.z * v2.x + p2.w * v3.x;
            acc[2][1] += p2.x * v0.y + p2.y * v1.y + p2.z * v2.y + p2.w * v3.y;
            acc[2][2] += p2.x * v0.z + p2.y * v1.z + p2.z * v2.z + p2.w * v3.z;
            acc[2][3] += p2.x * v0.w + p2.y * v1.w + p2.z * v2.w + p2.w * v3.w;
            acc[3][0] += p3.x * v0.x + p3.y * v1.x + p3.z * v2.x + p3.w * v3.x;
            acc[3][1] += p3.x * v0.y + p3.y * v1.y + p3.z * v2.y + p3.w * v3.y;
            acc[3][2] += p3.x * v0.z + p3.y * v1.z + p3.z * v2.z + p3.w * v3.z;
            acc[3][3] += p3.x * v0.w + p3.y * v1.w + p3.z * v2.w + p3.w * v3.w;
        }
    }

    float* Cg = g_C + ((size_t)(b * SEQ + qg0)) * D_MODEL + h * DK + (tx << 2);
#pragma unroll
    for (int i = 0; i < 4; i++) {
        float inv = 1.0f / lsum[i];
        *(float4*)(Cg + (size_t)i * D_MODEL) =
            make_float4(acc[i][0] * inv, acc[i][1] * inv, acc[i][2] * inv, acc[i][3] * inv);
    }
}

// ---------------------------------------------------------------------------
extern "C" void kernel_launch(void* const* d_in, const int* in_sizes, int n_in,
                              void* d_out, int out_size)
{
    const float* q    = (const float*)d_in[0];
    const float* k    = (const float*)d_in[1];
    const float* v    = (const float*)d_in[2];
    const int*   mask = (const int*)  d_in[3];
    const float* wq   = (const float*)d_in[4];
    const float* bq   = (const float*)d_in[5];
    const float* wk   = (const float*)d_in[6];
    const float* bk   = (const float*)d_in[7];
    const float* wv   = (const float*)d_in[8];
    const float* bv   = (const float*)d_in[9];
    const float* wo   = (const float*)d_in[10];
    const float* bo   = (const float*)d_in[11];
    float* out = (float*)d_out;

    float *gQ, *gK, *gV, *gC;
    cudaGetSymbolAddress((void**)&gQ, g_Q);
    cudaGetSymbolAddress((void**)&gK, g_K);
    cudaGetSymbolAddress((void**)&gV, g_V);
    cudaGetSymbolAddress((void**)&gC, g_C);

    cudaFuncSetAttribute(gemm_mma_kernel,
                         cudaFuncAttributeMaxDynamicSharedMemorySize, GEMM_SMEM);
    const int attn_smem = (2 * 64 * 64 + 2 * 64 * 68) * (int)sizeof(float); // 67584
    cudaFuncSetAttribute(attn_kernel,
                         cudaFuncAttributeMaxDynamicSharedMemorySize, attn_smem);

    dim3 gemm_grid(D_MODEL / 128, M_TOT / 128);   // (8, 32) = 256 CTAs
    gemm_mma_kernel<<<gemm_grid, 256, GEMM_SMEM>>>(q, wq, bq, gQ);
    gemm_mma_kernel<<<gemm_grid, 256, GEMM_SMEM>>>(k, wk, bk, gK);
    gemm_mma_kernel<<<gemm_grid, 256, GEMM_SMEM>>>(v, wv, bv, gV);

    dim3 attn_grid(SEQ / 64, NHEAD, BATCH);       // (32, 16, 2)
    attn_kernel<<<attn_grid, 256, attn_smem>>>(mask);

    gemm_mma_kernel<<<gemm_grid, 256, GEMM_SMEM>>>(gC, wo, bo, out);
}

// round 4
// speedup vs baseline: 2.5550x; 1.6863x over previous
#include <cuda_runtime.h>
#include <cuda_bf16.h>
#include <cstdint>
#include <cstddef>

#define D_MODEL 1024
#define NHEAD   16
#define DK      64
#define BATCH   2
#define SEQ     2048
#define M_TOT   (BATCH * SEQ)   // 4096

// Scratch (allocation-free: __device__ globals)
__device__ float g_Q[(size_t)M_TOT * D_MODEL];
__device__ float g_K[(size_t)M_TOT * D_MODEL];
__device__ float g_V[(size_t)M_TOT * D_MODEL];
__device__ float g_C[(size_t)M_TOT * D_MODEL];

// ===========================================================================
// Helpers (baseline PTX ISA only — compute_103-safe, no sm_103a features)
// ===========================================================================
__device__ __forceinline__ uint32_t smem_u32(const void* p) {
    uint32_t a;
    asm("{ .reg .u64 t; cvta.to.shared.u64 t, %1; cvt.u32.u64 %0, t; }"
        : "=r"(a) : "l"(p));
    return a;
}

#define LDM4(r, addr) \
    asm volatile("ldmatrix.sync.aligned.m8n8.x4.shared.b16 {%0,%1,%2,%3}, [%4];" \
        : "=r"((r)[0]), "=r"((r)[1]), "=r"((r)[2]), "=r"((r)[3]) : "r"(addr))

#define LDM4_T(r, addr) \
    asm volatile("ldmatrix.sync.aligned.m8n8.x4.trans.shared.b16 {%0,%1,%2,%3}, [%4];" \
        : "=r"((r)[0]), "=r"((r)[1]), "=r"((r)[2]), "=r"((r)[3]) : "r"(addr))

#define MMA_BF16(d, a, b0, b1) \
    asm volatile("mma.sync.aligned.m16n8k16.row.col.f32.bf16.bf16.f32 " \
        "{%0,%1,%2,%3}, {%4,%5,%6,%7}, {%8,%9}, {%0,%1,%2,%3};" \
        : "+f"((d)[0]), "+f"((d)[1]), "+f"((d)[2]), "+f"((d)[3]) \
        : "r"((a)[0]), "r"((a)[1]), "r"((a)[2]), "r"((a)[3]), "r"(b0), "r"(b1))

__device__ __forceinline__ uint32_t pack_bf16(float a, float b) {
    __nv_bfloat162 h = __floats2bfloat162_rn(a, b);
    return *(uint32_t*)&h;
}
__device__ __forceinline__ uint32_t pack_bf16_lo(float a, float b) {
    float ra = a - __bfloat162float(__float2bfloat16_rn(a));
    float rb = b - __bfloat162float(__float2bfloat16_rn(b));
    return pack_bf16(ra, rb);
}

// fp32 -> (hi bf16, lo bf16) split, 4 elements packed into two uint2
__device__ __forceinline__ void cvt4_split(float4 f, uint2& hi, uint2& lo) {
    __nv_bfloat16 h0 = __float2bfloat16_rn(f.x);
    __nv_bfloat16 h1 = __float2bfloat16_rn(f.y);
    __nv_bfloat16 h2 = __float2bfloat16_rn(f.z);
    __nv_bfloat16 h3 = __float2bfloat16_rn(f.w);
    __nv_bfloat16 l0 = __float2bfloat16_rn(f.x - __bfloat162float(h0));
    __nv_bfloat16 l1 = __float2bfloat16_rn(f.y - __bfloat162float(h1));
    __nv_bfloat16 l2 = __float2bfloat16_rn(f.z - __bfloat162float(h2));
    __nv_bfloat16 l3 = __float2bfloat16_rn(f.w - __bfloat162float(h3));
    __nv_bfloat162 p0; p0.x = h0; p0.y = h1;
    __nv_bfloat162 p1; p1.x = h2; p1.y = h3;
    __nv_bfloat162 p2; p2.x = l0; p2.y = l1;
    __nv_bfloat162 p3; p3.x = l2; p3.y = l3;
    hi.x = *(uint32_t*)&p0; hi.y = *(uint32_t*)&p1;
    lo.x = *(uint32_t*)&p2; lo.y = *(uint32_t*)&p3;
}

// ===========================================================================
// Tensor-core GEMM (mma.sync bf16, 2-term split): Y[4096,1024] = X @ W^T + b
// (round-3 proven kernel, unchanged)
// ===========================================================================
#define RS        80
#define TILE_SZ   10240
#define BUF_SZ    40960
#define GEMM_SMEM 81920

__global__ __launch_bounds__(256) void gemm_mma_kernel(
    const float* __restrict__ X, const float* __restrict__ W,
    const float* __restrict__ bias, float* __restrict__ Y)
{
    extern __shared__ char sm[];
    const uint32_t sb = smem_u32(sm);
    const int t    = threadIdx.x;
    const int lane = t & 31;
    const int wid  = t >> 5;
    const int wm   = (wid & 1) << 6;
    const int wn   = (wid >> 1) << 5;
    const int m0 = blockIdx.y << 7;
    const int n0 = blockIdx.x << 7;

    float4 ra[4], rb[4];

    auto g_load = [&](int k0) {
#pragma unroll
        for (int i = 0; i < 4; i++) {
            const int idx = t + (i << 8);
            const int r = idx >> 3, c = idx & 7;
            ra[i] = *(const float4*)(X + (size_t)(m0 + r) * D_MODEL + k0 + (c << 2));
            rb[i] = *(const float4*)(W + (size_t)(n0 + r) * D_MODEL + k0 + (c << 2));
        }
    };
    auto s_store = [&](int base) {
#pragma unroll
        for (int i = 0; i < 4; i++) {
            const int idx = t + (i << 8);
            const int r = idx >> 3, c = idx & 7;
            const int off = r * RS + (c << 3);
            uint2 hi, lo;
            cvt4_split(ra[i], hi, lo);
            *(uint2*)(sm + base + off)           = hi;
            *(uint2*)(sm + base + TILE_SZ + off) = lo;
            cvt4_split(rb[i], hi, lo);
            *(uint2*)(sm + base + 2 * TILE_SZ + off) = hi;
            *(uint2*)(sm + base + 3 * TILE_SZ + off) = lo;
        }
    };

    float acc[4][4][4] = {};

    g_load(0);
    s_store(0);
    __syncthreads();

    for (int kt = 0; kt < D_MODEL / 32; kt++) {
        if (kt < 31) g_load((kt + 1) << 5);

        const uint32_t buf = sb + (kt & 1) * BUF_SZ;
#pragma unroll
        for (int ks = 0; ks < 2; ks++) {
            const int kb = ks << 5;
            uint32_t a_hi[4][4], a_lo[4][4];
            uint32_t b_hi[4][2], b_lo[4][2];
#pragma unroll
            for (int mi = 0; mi < 4; mi++) {
                const uint32_t r = wm + (mi << 4) + (lane & 15);
                const uint32_t ad = buf + r * RS + kb + ((lane >> 4) << 4);
                LDM4(a_hi[mi], ad);
                LDM4(a_lo[mi], ad + TILE_SZ);
            }
#pragma unroll
            for (int p = 0; p < 2; p++) {
                const uint32_t nr = wn + (p << 4) + (lane & 7) + ((lane >> 4) << 3);
                const uint32_t ad = buf + 2 * TILE_SZ + nr * RS + kb + (((lane >> 3) & 1) << 4);
                uint32_t q[4];
                LDM4(q, ad);
                b_hi[2 * p][0] = q[0]; b_hi[2 * p][1] = q[1];
                b_hi[2 * p + 1][0] = q[2]; b_hi[2 * p + 1][1] = q[3];
                LDM4(q, ad + TILE_SZ);
                b_lo[2 * p][0] = q[0]; b_lo[2 * p][1] = q[1];
                b_lo[2 * p + 1][0] = q[2]; b_lo[2 * p + 1][1] = q[3];
            }
#pragma unroll
            for (int mi = 0; mi < 4; mi++)
#pragma unroll
                for (int ni = 0; ni < 4; ni++) {
                    MMA_BF16(acc[mi][ni], a_hi[mi], b_hi[ni][0], b_hi[ni][1]);
                    MMA_BF16(acc[mi][ni], a_hi[mi], b_lo[ni][0], b_lo[ni][1]);
                    MMA_BF16(acc[mi][ni], a_lo[mi], b_hi[ni][0], b_hi[ni][1]);
                }
        }

        if (kt < 31) {
            s_store(((kt + 1) & 1) * BUF_SZ);
            __syncthreads();
        }
    }

    const int lr4 = lane >> 2;
    const int lc2 = (lane & 3) << 1;
#pragma unroll
    for (int mi = 0; mi < 4; mi++) {
        const int r = m0 + wm + (mi << 4) + lr4;
#pragma unroll
        for (int ni = 0; ni < 4; ni++) {
            const int c = n0 + wn + (ni << 3) + lc2;
            const float bx = bias[c], by = bias[c + 1];
            float2 o0, o1;
            o0.x = acc[mi][ni][0] + bx; o0.y = acc[mi][ni][1] + by;
            o1.x = acc[mi][ni][2] + bx; o1.y = acc[mi][ni][3] + by;
            *(float2*)(Y + (size_t)r * D_MODEL + c)       = o0;
            *(float2*)(Y + (size_t)(r + 8) * D_MODEL + c) = o1;
        }
    }
}

// ===========================================================================
// Tensor-core flash attention (mma.sync bf16, 2-term split).
// Block: 128 queries x (head, batch), 8 warps; warp = 16 q rows x 64 keys.
// Q A-frags live in registers for the whole block. K/V double-buffered smem.
// S accumulator frags re-pack directly into P A-frags (no smem round trip).
// V B-frags via ldmatrix.trans on row-major [key][dim] tiles.
// smem: Qhi/Qlo 128x144B (36864) + 2 x (Khi,Klo,Vhi,Vlo 64x144B) (73728).
// ===========================================================================
#define ARS     144
#define A_QLO   18432
#define A_KV    36864
#define A_KVB   36864     // per buffer
#define AO_KLO  9216
#define AO_VHI  18432
#define AO_VLO  27648
#define ATT_SMEM 110592

__global__ __launch_bounds__(256) void attn_mma_kernel(const int* __restrict__ mask)
{
    extern __shared__ char sm[];
    const uint32_t sb = smem_u32(sm);
    const int t    = threadIdx.x;
    const int lane = t & 31;
    const int w    = t >> 5;
    const int b  = blockIdx.z;
    const int h  = blockIdx.y;
    const int q0 = blockIdx.x << 7;

    // ---- stage Q tile (128 x 64) hi/lo into smem ----
#pragma unroll
    for (int i = 0; i < 8; i++) {
        const int idx = t + (i << 8);
        const int row = idx >> 4;
        const int c4  = idx & 15;
        float4 f = *(const float4*)(g_Q + (size_t)(b * SEQ + q0 + row) * D_MODEL
                                    + h * DK + (c4 << 2));
        uint2 hi, lo;
        cvt4_split(f, hi, lo);
        const int off = row * ARS + (c4 << 3);
        *(uint2*)(sm + off)          = hi;
        *(uint2*)(sm + A_QLO + off)  = lo;
    }
    __syncthreads();

    // ---- Q A-frags to registers (warp w: q rows w*16 .. w*16+15) ----
    uint32_t Qh[4][4], Ql[4][4];
    {
        const uint32_t r = (w << 4) + (lane & 15);
#pragma unroll
        for (int ks = 0; ks < 4; ks++) {
            const uint32_t ad = sb + r * ARS + (ks << 5) + ((lane >> 4) << 4);
            LDM4(Qh[ks], ad);
            LDM4(Ql[ks], ad + A_QLO);
        }
    }

    float O[8][4] = {};
    float m0 = -1e30f, m1 = -1e30f, l0 = 0.0f, l1 = 0.0f;

    const float* Kg = g_K + (size_t)(b * SEQ) * D_MODEL + h * DK;
    const float* Vg = g_V + (size_t)(b * SEQ) * D_MODEL + h * DK;

    float4 rk[4], rv[4];
    auto g_load = [&](int kt) {
        const int k0 = kt << 6;
#pragma unroll
        for (int i = 0; i < 4; i++) {
            const int idx = t + (i << 8);
            const int row = idx >> 4;
            const int c4  = idx & 15;
            rk[i] = *(const float4*)(Kg + (size_t)(k0 + row) * D_MODEL + (c4 << 2));
            rv[i] = *(const float4*)(Vg + (size_t)(k0 + row) * D_MODEL + (c4 << 2));
        }
    };
    auto s_store = [&](int bi) {
        const int base = A_KV + bi * A_KVB;
#pragma unroll
        for (int i = 0; i < 4; i++) {
            const int idx = t + (i << 8);
            const int row = idx >> 4;
            const int c4  = idx & 15;
            const int off = row * ARS + (c4 << 3);
            uint2 hi, lo;
            cvt4_split(rk[i], hi, lo);
            *(uint2*)(sm + base + off)          = hi;
            *(uint2*)(sm + base + AO_KLO + off) = lo;
            cvt4_split(rv[i], hi, lo);
            *(uint2*)(sm + base + AO_VHI + off) = hi;
            *(uint2*)(sm + base + AO_VLO + off) = lo;
        }
    };

    g_load(0);
    s_store(0);
    __syncthreads();

    const int qr = q0 + (w << 4) + (lane >> 2);  // this thread's even q row
    const int kc = (lane & 3) << 1;

    for (int kt = 0; kt < SEQ / 64; kt++) {       // 32 key tiles
        if (kt < 31) g_load(kt + 1);
        const uint32_t kb = sb + A_KV + (kt & 1) * A_KVB;

        // ---- S = Q . K^T  (16 x 64 per warp) ----
        float S[8][4] = {};
#pragma unroll
        for (int ks = 0; ks < 4; ks++) {
#pragma unroll
            for (int g = 0; g < 4; g++) {
                const uint32_t nr = (g << 4) + (lane & 7) + ((lane >> 4) << 3);
                const uint32_t ad = kb + nr * ARS + (ks << 5) + (((lane >> 3) & 1) << 4);
                uint32_t kh[4], kl[4];
                LDM4(kh, ad);
                LDM4(kl, ad + AO_KLO);
                MMA_BF16(S[2 * g],     Qh[ks], kh[0], kh[1]);
                MMA_BF16(S[2 * g],     Qh[ks], kl[0], kl[1]);
                MMA_BF16(S[2 * g],     Ql[ks], kh[0], kh[1]);
                MMA_BF16(S[2 * g + 1], Qh[ks], kh[2], kh[3]);
                MMA_BF16(S[2 * g + 1], Qh[ks], kl[2], kl[3]);
                MMA_BF16(S[2 * g + 1], Ql[ks], kh[2], kh[3]);
            }
        }

        // ---- scale + soft mask ----
        const int kcol = (kt << 6) + kc;
        const int* mp0 = mask + (size_t)qr * SEQ + kcol;
        const int* mp1 = mp0 + (size_t)8 * SEQ;
        int2 mk0[8], mk1[8];
#pragma unroll
        for (int j = 0; j < 8; j++) {
            mk0[j] = *(const int2*)(mp0 + (j << 3));
            mk1[j] = *(const int2*)(mp1 + (j << 3));
        }
#pragma unroll
        for (int j = 0; j < 8; j++) {
            S[j][0] = mk0[j].x ? S[j][0] * 0.125f : -1.0f;
            S[j][1] = mk0[j].y ? S[j][1] * 0.125f : -1.0f;
            S[j][2] = mk1[j].x ? S[j][2] * 0.125f : -1.0f;
            S[j][3] = mk1[j].y ? S[j][3] * 0.125f : -1.0f;
        }

        // ---- online softmax (rows qr and qr+8) ----
        float tm0 = -1e30f, tm1 = -1e30f;
#pragma unroll
        for (int j = 0; j < 8; j++) {
            tm0 = fmaxf(tm0, fmaxf(S[j][0], S[j][1]));
            tm1 = fmaxf(tm1, fmaxf(S[j][2], S[j][3]));
        }
        tm0 = fmaxf(tm0, __shfl_xor_sync(0xffffffffu, tm0, 1));
        tm0 = fmaxf(tm0, __shfl_xor_sync(0xffffffffu, tm0, 2));
        tm1 = fmaxf(tm1, __shfl_xor_sync(0xffffffffu, tm1, 1));
        tm1 = fmaxf(tm1, __shfl_xor_sync(0xffffffffu, tm1, 2));
        const float mn0 = fmaxf(m0, tm0);
        const float mn1 = fmaxf(m1, tm1);
        const float a0 = __expf(m0 - mn0);
        const float a1 = __expf(m1 - mn1);
        float rs0 = 0.0f, rs1 = 0.0f;
        float P[8][4];
#pragma unroll
        for (int j = 0; j < 8; j++) {
            P[j][0] = __expf(S[j][0] - mn0);
            P[j][1] = __expf(S[j][1] - mn0);
            P[j][2] = __expf(S[j][2] - mn1);
            P[j][3] = __expf(S[j][3] - mn1);
            rs0 += P[j][0] + P[j][1];
            rs1 += P[j][2] + P[j][3];
        }
        rs0 += __shfl_xor_sync(0xffffffffu, rs0, 1);
        rs0 += __shfl_xor_sync(0xffffffffu, rs0, 2);
        rs1 += __shfl_xor_sync(0xffffffffu, rs1, 1);
        rs1 += __shfl_xor_sync(0xffffffffu, rs1, 2);
        l0 = l0 * a0 + rs0;
        l1 = l1 * a1 + rs1;
        m0 = mn0; m1 = mn1;
#pragma unroll
        for (int j = 0; j < 8; j++) {
            O[j][0] *= a0; O[j][1] *= a0;
            O[j][2] *= a1; O[j][3] *= a1;
        }

        // ---- re-pack P into A-frags (hi/lo) ----
        uint32_t Ph[4][4], Pl[4][4];
#pragma unroll
        for (int tt = 0; tt < 4; tt++) {
            const float* p0 = P[2 * tt];
            const float* p1 = P[2 * tt + 1];
            Ph[tt][0] = pack_bf16(p0[0], p0[1]);
            Ph[tt][1] = pack_bf16(p0[2], p0[3]);
            Ph[tt][2] = pack_bf16(p1[0], p1[1]);
            Ph[tt][3] = pack_bf16(p1[2], p1[3]);
            Pl[tt][0] = pack_bf16_lo(p0[0], p0[1]);
            Pl[tt][1] = pack_bf16_lo(p0[2], p0[3]);
            Pl[tt][2] = pack_bf16_lo(p1[0], p1[1]);
            Pl[tt][3] = pack_bf16_lo(p1[2], p1[3]);
        }

        // ---- O += P . V  (V B-frags via ldmatrix.trans) ----
#pragma unroll
        for (int tt = 0; tt < 4; tt++) {
#pragma unroll
            for (int g = 0; g < 4; g++) {
                const uint32_t ad = kb + AO_VHI
                    + ((tt << 4) + (lane & 15)) * ARS
                    + (g << 5) + ((lane >> 4) << 4);
                uint32_t vh[4], vl[4];
                LDM4_T(vh, ad);
                LDM4_T(vl, ad + 9216);
                MMA_BF16(O[2 * g],     Ph[tt], vh[0], vh[1]);
                MMA_BF16(O[2 * g],     Ph[tt], vl[0], vl[1]);
                MMA_BF16(O[2 * g],     Pl[tt], vh[0], vh[1]);
                MMA_BF16(O[2 * g + 1], Ph[tt], vh[2], vh[3]);
                MMA_BF16(O[2 * g + 1], Ph[tt], vl[2], vl[3]);
                MMA_BF16(O[2 * g + 1], Pl[tt], vh[2], vh[3]);
            }
        }

        if (kt < 31) s_store((kt + 1) & 1);
        __syncthreads();
    }

    // ---- normalize + write context [B,S,H*DK] ----
    const float i0 = 1.0f / l0;
    const float i1 = 1.0f / l1;
    float* C0 = g_C + (size_t)(b * SEQ + qr) * D_MODEL + h * DK + kc;
    float* C1 = C0 + (size_t)8 * D_MODEL;
#pragma unroll
    for (int j = 0; j < 8; j++) {
        float2 o0, o1;
        o0.x = O[j][0] * i0; o0.y = O[j][1] * i0;
        o1.x = O[j][2] * i1; o1.y = O[j][3] * i1;
        *(float2*)(C0 + (j << 3)) = o0;
        *(float2*)(C1 + (j << 3)) = o1;
    }
}

// ---------------------------------------------------------------------------
extern "C" void kernel_launch(void* const* d_in, const int* in_sizes, int n_in,
                              void* d_out, int out_size)
{
    const float* q    = (const float*)d_in[0];
    const float* k    = (const float*)d_in[1];
    const float* v    = (const float*)d_in[2];
    const int*   mask = (const int*)  d_in[3];
    const float* wq   = (const float*)d_in[4];
    const float* bq   = (const float*)d_in[5];
    const float* wk   = (const float*)d_in[6];
    const float* bk   = (const float*)d_in[7];
    const float* wv   = (const float*)d_in[8];
    const float* bv   = (const float*)d_in[9];
    const float* wo   = (const float*)d_in[10];
    const float* bo   = (const float*)d_in[11];
    float* out = (float*)d_out;

    float *gQ, *gK, *gV, *gC;
    cudaGetSymbolAddress((void**)&gQ, g_Q);
    cudaGetSymbolAddress((void**)&gK, g_K);
    cudaGetSymbolAddress((void**)&gV, g_V);
    cudaGetSymbolAddress((void**)&gC, g_C);

    cudaFuncSetAttribute(gemm_mma_kernel,
                         cudaFuncAttributeMaxDynamicSharedMemorySize, GEMM_SMEM);
    cudaFuncSetAttribute(attn_mma_kernel,
                         cudaFuncAttributeMaxDynamicSharedMemorySize, ATT_SMEM);

    dim3 gemm_grid(D_MODEL / 128, M_TOT / 128);   // (8, 32) = 256 CTAs
    gemm_mma_kernel<<<gemm_grid, 256, GEMM_SMEM>>>(q, wq, bq, gQ);
    gemm_mma_kernel<<<gemm_grid, 256, GEMM_SMEM>>>(k, wk, bk, gK);
    gemm_mma_kernel<<<gemm_grid, 256, GEMM_SMEM>>>(v, wv, bv, gV);

    dim3 attn_grid(SEQ / 128, NHEAD, BATCH);      // (16, 16, 2) = 512 CTAs
    attn_mma_kernel<<<attn_grid, 256, ATT_SMEM>>>(mask);

    gemm_mma_kernel<<<gemm_grid, 256, GEMM_SMEM>>>(gC, wo, bo, out);
}

// round 5
// speedup vs baseline: 2.9176x; 1.1419x over previous
#include <cuda_runtime.h>
#include <cuda_bf16.h>
#include <cstdint>
#include <cstddef>

#define D_MODEL 1024
#define NHEAD   16
#define DK      64
#define BATCH   2
#define SEQ     2048
#define M_TOT   (BATCH * SEQ)   // 4096

// Scratch (allocation-free: __device__ globals)
__device__ __nv_bfloat16 g_Qh[(size_t)M_TOT * D_MODEL];
__device__ __nv_bfloat16 g_Ql[(size_t)M_TOT * D_MODEL];
__device__ __nv_bfloat16 g_Kh[(size_t)M_TOT * D_MODEL];
__device__ __nv_bfloat16 g_Kl[(size_t)M_TOT * D_MODEL];
__device__ __nv_bfloat16 g_Vh[(size_t)M_TOT * D_MODEL];
__device__ __nv_bfloat16 g_Vl[(size_t)M_TOT * D_MODEL];
__device__ float         g_C [(size_t)M_TOT * D_MODEL];
__device__ unsigned char g_mask8[(size_t)SEQ * SEQ];

// ===========================================================================
// Helpers (baseline PTX ISA only — compute_103-safe)
// ===========================================================================
__device__ __forceinline__ uint32_t smem_u32(const void* p) {
    uint32_t a;
    asm("{ .reg .u64 t; cvta.to.shared.u64 t, %1; cvt.u32.u64 %0, t; }"
        : "=r"(a) : "l"(p));
    return a;
}

#define LDM4(r, addr) \
    asm volatile("ldmatrix.sync.aligned.m8n8.x4.shared.b16 {%0,%1,%2,%3}, [%4];" \
        : "=r"((r)[0]), "=r"((r)[1]), "=r"((r)[2]), "=r"((r)[3]) : "r"(addr))

#define LDM4_T(r, addr) \
    asm volatile("ldmatrix.sync.aligned.m8n8.x4.trans.shared.b16 {%0,%1,%2,%3}, [%4];" \
        : "=r"((r)[0]), "=r"((r)[1]), "=r"((r)[2]), "=r"((r)[3]) : "r"(addr))

#define MMA_BF16(d, a, b0, b1) \
    asm volatile("mma.sync.aligned.m16n8k16.row.col.f32.bf16.bf16.f32 " \
        "{%0,%1,%2,%3}, {%4,%5,%6,%7}, {%8,%9}, {%0,%1,%2,%3};" \
        : "+f"((d)[0]), "+f"((d)[1]), "+f"((d)[2]), "+f"((d)[3]) \
        : "r"((a)[0]), "r"((a)[1]), "r"((a)[2]), "r"((a)[3]), "r"(b0), "r"(b1))

#define CP16(sa, gp) \
    asm volatile("{ .reg .u64 g; cvta.to.global.u64 g, %1; " \
                 "cp.async.cg.shared.global [%0], [g], 16; }" \
        :: "r"((uint32_t)(sa)), "l"(gp) : "memory")
#define CP_COMMIT  asm volatile("cp.async.commit_group;" ::: "memory")
#define CP_WAIT1   asm volatile("cp.async.wait_group 1;" ::: "memory")
#define CP_WAIT0   asm volatile("cp.async.wait_group 0;" ::: "memory")

__device__ __forceinline__ uint32_t pack_bf16(float a, float b) {
    __nv_bfloat162 h = __floats2bfloat162_rn(a, b);
    return *(uint32_t*)&h;
}
__device__ __forceinline__ uint32_t pack_bf16_lo(float a, float b) {
    float ra = a - __bfloat162float(__float2bfloat16_rn(a));
    float rb = b - __bfloat162float(__float2bfloat16_rn(b));
    return pack_bf16(ra, rb);
}

// fp32 -> (hi bf16, lo bf16) split, 4 elements packed into two uint2
__device__ __forceinline__ void cvt4_split(float4 f, uint2& hi, uint2& lo) {
    hi.x = pack_bf16(f.x, f.y);  hi.y = pack_bf16(f.z, f.w);
    lo.x = pack_bf16_lo(f.x, f.y); lo.y = pack_bf16_lo(f.z, f.w);
}

// XOR swizzle: row-major 128B rows, 16B chunks permuted within row
__device__ __forceinline__ uint32_t swz(uint32_t row, uint32_t chunk) {
    return (row << 7) + ((chunk ^ (row & 7)) << 4);
}

// ===========================================================================
// mask int32 -> u8 pre-pass (4M elements)
// ===========================================================================
__global__ void mask8_kernel(const int* __restrict__ m)
{
    const size_t i = ((size_t)blockIdx.x * 256 + threadIdx.x) << 2;
    int4 v = *(const int4*)(m + i);
    uchar4 o;
    o.x = (unsigned char)v.x; o.y = (unsigned char)v.y;
    o.z = (unsigned char)v.z; o.w = (unsigned char)v.w;
    *(uchar4*)(g_mask8 + i) = o;
}

// ===========================================================================
// Tensor-core GEMM (mma.sync bf16, 2-term split): Y = X @ W^T + b
// Epilogue modes: Yf != nullptr -> fp32 out; else bf16 hi/lo planes (Yh, Yl).
// ===========================================================================
#define RS        80
#define TILE_SZ   10240
#define BUF_SZ    40960
#define GEMM_SMEM 81920

__global__ __launch_bounds__(256) void gemm_mma_kernel(
    const float* __restrict__ X, const float* __restrict__ W,
    const float* __restrict__ bias, float* __restrict__ Yf,
    __nv_bfloat16* __restrict__ Yh, __nv_bfloat16* __restrict__ Yl)
{
    extern __shared__ char sm[];
    const uint32_t sb = smem_u32(sm);
    const int t    = threadIdx.x;
    const int lane = t & 31;
    const int wid  = t >> 5;
    const int wm   = (wid & 1) << 6;
    const int wn   = (wid >> 1) << 5;
    const int m0 = blockIdx.y << 7;
    const int n0 = blockIdx.x << 7;

    float4 ra[4], rb[4];

    auto g_load = [&](int k0) {
#pragma unroll
        for (int i = 0; i < 4; i++) {
            const int idx = t + (i << 8);
            const int r = idx >> 3, c = idx & 7;
            ra[i] = *(const float4*)(X + (size_t)(m0 + r) * D_MODEL + k0 + (c << 2));
            rb[i] = *(const float4*)(W + (size_t)(n0 + r) * D_MODEL + k0 + (c << 2));
        }
    };
    auto s_store = [&](int base) {
#pragma unroll
        for (int i = 0; i < 4; i++) {
            const int idx = t + (i << 8);
            const int r = idx >> 3, c = idx & 7;
            const int off = r * RS + (c << 3);
            uint2 hi, lo;
            cvt4_split(ra[i], hi, lo);
            *(uint2*)(sm + base + off)           = hi;
            *(uint2*)(sm + base + TILE_SZ + off) = lo;
            cvt4_split(rb[i], hi, lo);
            *(uint2*)(sm + base + 2 * TILE_SZ + off) = hi;
            *(uint2*)(sm + base + 3 * TILE_SZ + off) = lo;
        }
    };

    float acc[4][4][4] = {};

    g_load(0);
    s_store(0);
    __syncthreads();

    for (int kt = 0; kt < D_MODEL / 32; kt++) {
        if (kt < 31) g_load((kt + 1) << 5);

        const uint32_t buf = sb + (kt & 1) * BUF_SZ;
#pragma unroll
        for (int ks = 0; ks < 2; ks++) {
            const int kb = ks << 5;
            uint32_t a_hi[4][4], a_lo[4][4];
            uint32_t b_hi[4][2], b_lo[4][2];
#pragma unroll
            for (int mi = 0; mi < 4; mi++) {
                const uint32_t r = wm + (mi << 4) + (lane & 15);
                const uint32_t ad = buf + r * RS + kb + ((lane >> 4) << 4);
                LDM4(a_hi[mi], ad);
                LDM4(a_lo[mi], ad + TILE_SZ);
            }
#pragma unroll
            for (int p = 0; p < 2; p++) {
                const uint32_t nr = wn + (p << 4) + (lane & 7) + ((lane >> 4) << 3);
                const uint32_t ad = buf + 2 * TILE_SZ + nr * RS + kb + (((lane >> 3) & 1) << 4);
                uint32_t q[4];
                LDM4(q, ad);
                b_hi[2 * p][0] = q[0]; b_hi[2 * p][1] = q[1];
                b_hi[2 * p + 1][0] = q[2]; b_hi[2 * p + 1][1] = q[3];
                LDM4(q, ad + TILE_SZ);
                b_lo[2 * p][0] = q[0]; b_lo[2 * p][1] = q[1];
                b_lo[2 * p + 1][0] = q[2]; b_lo[2 * p + 1][1] = q[3];
            }
#pragma unroll
            for (int mi = 0; mi < 4; mi++)
#pragma unroll
                for (int ni = 0; ni < 4; ni++) {
                    MMA_BF16(acc[mi][ni], a_hi[mi], b_hi[ni][0], b_hi[ni][1]);
                    MMA_BF16(acc[mi][ni], a_hi[mi], b_lo[ni][0], b_lo[ni][1]);
                    MMA_BF16(acc[mi][ni], a_lo[mi], b_hi[ni][0], b_hi[ni][1]);
                }
        }

        if (kt < 31) {
            s_store(((kt + 1) & 1) * BUF_SZ);
            __syncthreads();
        }
    }

    const int lr4 = lane >> 2;
    const int lc2 = (lane & 3) << 1;
    if (Yf) {
#pragma unroll
        for (int mi = 0; mi < 4; mi++) {
            const int r = m0 + wm + (mi << 4) + lr4;
#pragma unroll
            for (int ni = 0; ni < 4; ni++) {
                const int c = n0 + wn + (ni << 3) + lc2;
                const float bx = bias[c], by = bias[c + 1];
                float2 o0, o1;
                o0.x = acc[mi][ni][0] + bx; o0.y = acc[mi][ni][1] + by;
                o1.x = acc[mi][ni][2] + bx; o1.y = acc[mi][ni][3] + by;
                *(float2*)(Yf + (size_t)r * D_MODEL + c)       = o0;
                *(float2*)(Yf + (size_t)(r + 8) * D_MODEL + c) = o1;
            }
        }
    } else {
#pragma unroll
        for (int mi = 0; mi < 4; mi++) {
            const int r = m0 + wm + (mi << 4) + lr4;
#pragma unroll
            for (int ni = 0; ni < 4; ni++) {
                const int c = n0 + wn + (ni << 3) + lc2;
                const float bx = bias[c], by = bias[c + 1];
                const float v0 = acc[mi][ni][0] + bx, v1 = acc[mi][ni][1] + by;
                const float v2 = acc[mi][ni][2] + bx, v3 = acc[mi][ni][3] + by;
                *(uint32_t*)(Yh + (size_t)r * D_MODEL + c)       = pack_bf16(v0, v1);
                *(uint32_t*)(Yl + (size_t)r * D_MODEL + c)       = pack_bf16_lo(v0, v1);
                *(uint32_t*)(Yh + (size_t)(r + 8) * D_MODEL + c) = pack_bf16(v2, v3);
                *(uint32_t*)(Yl + (size_t)(r + 8) * D_MODEL + c) = pack_bf16_lo(v2, v3);
            }
        }
    }
}

// ===========================================================================
// Tensor-core flash attention v2:
//  - Q/K/V arrive pre-split bf16 (hi/lo planes) — zero conversion in kernel
//  - cp.async double-buffered K/V staging, XOR-swizzled (conflict-free ldmatrix)
//  - Q in smem, re-ldmatrix'd per k-step (saves 32 regs)
//  - mask as u8, __launch_bounds__(256,2) -> 2 CTAs/SM
// smem: Qh 16K | Ql 16K | 2 x stage(Kh 8K, Kl 8K, Vh 8K, Vl 8K) = 96 KB
// ===========================================================================
#define AS_QLO   16384
#define AS_STG   32768
#define AS_STGSZ 32768
#define AS_KLO   8192
#define AS_VHI   16384
#define AS_VLO   24576
#define ATT_SMEM 98304

__global__ __launch_bounds__(256, 2) void attn_mma_kernel()
{
    extern __shared__ char sm[];
    const uint32_t sb = smem_u32(sm);
    const int t    = threadIdx.x;
    const int lane = t & 31;
    const int w    = t >> 5;
    const int b  = blockIdx.z;
    const int h  = blockIdx.y;
    const int q0 = blockIdx.x << 7;
    const size_t bS   = (size_t)b * SEQ;
    const size_t hoff = (size_t)h * DK;

    // ---- stage issue helpers ----
    auto issue_stage = [&](int kt, int bufsel) {
        const uint32_t base = sb + AS_STG + bufsel * AS_STGSZ;
#pragma unroll
        for (int i = 0; i < 2; i++) {
            const int idx = t + (i << 8);
            const int row = idx >> 3, ch = idx & 7;
            const size_t go = (bS + (kt << 6) + row) * D_MODEL + hoff + (ch << 3);
            const uint32_t so = swz(row, ch);
            CP16(base + so,           g_Kh + go);
            CP16(base + AS_KLO + so,  g_Kl + go);
            CP16(base + AS_VHI + so,  g_Vh + go);
            CP16(base + AS_VLO + so,  g_Vl + go);
        }
    };

    // ---- prologue: Q + stage0 (group 0), stage1 (group 1) ----
#pragma unroll
    for (int i = 0; i < 4; i++) {
        const int idx = t + (i << 8);
        const int row = idx >> 3, ch = idx & 7;
        const size_t go = (bS + q0 + row) * D_MODEL + hoff + (ch << 3);
        const uint32_t so = swz(row, ch);
        CP16(sb + so,          g_Qh + go);
        CP16(sb + AS_QLO + so, g_Ql + go);
    }
    issue_stage(0, 0);
    CP_COMMIT;
    issue_stage(1, 1);
    CP_COMMIT;
    CP_WAIT1;
    __syncthreads();

    float O[8][4] = {};
    float m0 = -1e30f, m1 = -1e30f, l0 = 0.0f, l1 = 0.0f;

    const int qr = q0 + (w << 4) + (lane >> 2);
    const int kc = (lane & 3) << 1;

    for (int kt = 0; kt < SEQ / 64; kt++) {
        const uint32_t kb = sb + AS_STG + (kt & 1) * AS_STGSZ;

        // ---- S = Q . K^T ----
        float S[8][4] = {};
#pragma unroll
        for (int ks = 0; ks < 4; ks++) {
            uint32_t qh[4], ql[4];
            {
                const int row = (w << 4) + (lane & 15);
                const int ch  = (ks << 1) + (lane >> 4);
                const uint32_t qa = sb + swz(row, ch);
                LDM4(qh, qa);
                LDM4(ql, qa + AS_QLO);
            }
#pragma unroll
            for (int g = 0; g < 4; g++) {
                const int nr = (g << 4) + (lane & 7) + ((lane >> 4) << 3);
                const int ch = (ks << 1) + ((lane >> 3) & 1);
                const uint32_t ka = kb + swz(nr, ch);
                uint32_t kh[4], kl[4];
                LDM4(kh, ka);
                LDM4(kl, ka + AS_KLO);
                MMA_BF16(S[2 * g],     qh, kh[0], kh[1]);
                MMA_BF16(S[2 * g],     qh, kl[0], kl[1]);
                MMA_BF16(S[2 * g],     ql, kh[0], kh[1]);
                MMA_BF16(S[2 * g + 1], qh, kh[2], kh[3]);
                MMA_BF16(S[2 * g + 1], qh, kl[2], kl[3]);
                MMA_BF16(S[2 * g + 1], ql, kh[2], kh[3]);
            }
        }

        // ---- scale + soft mask (u8) ----
        const unsigned char* mp0 = g_mask8 + (size_t)qr * SEQ + (kt << 6) + kc;
        const unsigned char* mp1 = mp0 + (size_t)8 * SEQ;
#pragma unroll
        for (int j = 0; j < 8; j++) {
            const unsigned short k0v = *(const unsigned short*)(mp0 + (j << 3));
            const unsigned short k1v = *(const unsigned short*)(mp1 + (j << 3));
            S[j][0] = (k0v & 0xff) ? S[j][0] * 0.125f : -1.0f;
            S[j][1] = (k0v >> 8)   ? S[j][1] * 0.125f : -1.0f;
            S[j][2] = (k1v & 0xff) ? S[j][2] * 0.125f : -1.0f;
            S[j][3] = (k1v >> 8)   ? S[j][3] * 0.125f : -1.0f;
        }

        // ---- online softmax (rows qr, qr+8); P written in place of S ----
        float tm0 = -1e30f, tm1 = -1e30f;
#pragma unroll
        for (int j = 0; j < 8; j++) {
            tm0 = fmaxf(tm0, fmaxf(S[j][0], S[j][1]));
            tm1 = fmaxf(tm1, fmaxf(S[j][2], S[j][3]));
        }
        tm0 = fmaxf(tm0, __shfl_xor_sync(0xffffffffu, tm0, 1));
        tm0 = fmaxf(tm0, __shfl_xor_sync(0xffffffffu, tm0, 2));
        tm1 = fmaxf(tm1, __shfl_xor_sync(0xffffffffu, tm1, 1));
        tm1 = fmaxf(tm1, __shfl_xor_sync(0xffffffffu, tm1, 2));
        const float mn0 = fmaxf(m0, tm0);
        const float mn1 = fmaxf(m1, tm1);
        const float a0 = __expf(m0 - mn0);
        const float a1 = __expf(m1 - mn1);
        float rs0 = 0.0f, rs1 = 0.0f;
#pragma unroll
        for (int j = 0; j < 8; j++) {
            S[j][0] = __expf(S[j][0] - mn0);
            S[j][1] = __expf(S[j][1] - mn0);
            S[j][2] = __expf(S[j][2] - mn1);
            S[j][3] = __expf(S[j][3] - mn1);
            rs0 += S[j][0] + S[j][1];
            rs1 += S[j][2] + S[j][3];
        }
        rs0 += __shfl_xor_sync(0xffffffffu, rs0, 1);
        rs0 += __shfl_xor_sync(0xffffffffu, rs0, 2);
        rs1 += __shfl_xor_sync(0xffffffffu, rs1, 1);
        rs1 += __shfl_xor_sync(0xffffffffu, rs1, 2);
        l0 = l0 * a0 + rs0;
        l1 = l1 * a1 + rs1;
        m0 = mn0; m1 = mn1;
#pragma unroll
        for (int j = 0; j < 8; j++) {
            O[j][0] *= a0; O[j][1] *= a0;
            O[j][2] *= a1; O[j][3] *= a1;
        }

        // ---- re-pack P into bf16 hi/lo A-frags ----
        uint32_t Ph[4][4], Pl[4][4];
#pragma unroll
        for (int tt = 0; tt < 4; tt++) {
            const float* p0 = S[2 * tt];
            const float* p1 = S[2 * tt + 1];
            Ph[tt][0] = pack_bf16(p0[0], p0[1]);
            Ph[tt][1] = pack_bf16(p0[2], p0[3]);
            Ph[tt][2] = pack_bf16(p1[0], p1[1]);
            Ph[tt][3] = pack_bf16(p1[2], p1[3]);
            Pl[tt][0] = pack_bf16_lo(p0[0], p0[1]);
            Pl[tt][1] = pack_bf16_lo(p0[2], p0[3]);
            Pl[tt][2] = pack_bf16_lo(p1[0], p1[1]);
            Pl[tt][3] = pack_bf16_lo(p1[2], p1[3]);
        }

        // ---- O += P . V ----
#pragma unroll
        for (int tt = 0; tt < 4; tt++) {
#pragma unroll
            for (int g = 0; g < 4; g++) {
                const int row = (tt << 4) + (lane & 15);
                const int ch  = (g << 1) + (lane >> 4);
                const uint32_t va = kb + AS_VHI + swz(row, ch);
                uint32_t vh[4], vl[4];
                LDM4_T(vh, va);
                LDM4_T(vl, va + 8192);
                MMA_BF16(O[2 * g],     Ph[tt], vh[0], vh[1]);
                MMA_BF16(O[2 * g],     Ph[tt], vl[0], vl[1]);
                MMA_BF16(O[2 * g],     Pl[tt], vh[0], vh[1]);
                MMA_BF16(O[2 * g + 1], Ph[tt], vh[2], vh[3]);
                MMA_BF16(O[2 * g + 1], Ph[tt], vl[2], vl[3]);
                MMA_BF16(O[2 * g + 1], Pl[tt], vh[2], vh[3]);
            }
        }

        // ---- pipeline advance ----
        if (kt < 30) {
            __syncthreads();                 // readers done with buf kt&1
            issue_stage(kt + 2, kt & 1);
            CP_COMMIT;
            CP_WAIT1;                        // stage kt+1 complete
            __syncthreads();
        } else if (kt == 30) {
            CP_WAIT0;
            __syncthreads();
        }
    }

    // ---- normalize + write context [B,S,H*DK] ----
    const float i0 = 1.0f / l0;
    const float i1 = 1.0f / l1;
    float* C0 = g_C + (bS + qr) * D_MODEL + hoff + kc;
    float* C1 = C0 + (size_t)8 * D_MODEL;
#pragma unroll
    for (int j = 0; j < 8; j++) {
        float2 o0, o1;
        o0.x = O[j][0] * i0; o0.y = O[j][1] * i0;
        o1.x = O[j][2] * i1; o1.y = O[j][3] * i1;
        *(float2*)(C0 + (j << 3)) = o0;
        *(float2*)(C1 + (j << 3)) = o1;
    }
}

// ---------------------------------------------------------------------------
extern "C" void kernel_launch(void* const* d_in, const int* in_sizes, int n_in,
                              void* d_out, int out_size)
{
    const float* q    = (const float*)d_in[0];
    const float* k    = (const float*)d_in[1];
    const float* v    = (const float*)d_in[2];
    const int*   mask = (const int*)  d_in[3];
    const float* wq   = (const float*)d_in[4];
    const float* bq   = (const float*)d_in[5];
    const float* wk   = (const float*)d_in[6];
    const float* bk   = (const float*)d_in[7];
    const float* wv   = (const float*)d_in[8];
    const float* bv   = (const float*)d_in[9];
    const float* wo   = (const float*)d_in[10];
    const float* bo   = (const float*)d_in[11];
    float* out = (float*)d_out;

    __nv_bfloat16 *gQh, *gQl, *gKh, *gKl, *gVh, *gVl;
    float* gC;
    cudaGetSymbolAddress((void**)&gQh, g_Qh);
    cudaGetSymbolAddress((void**)&gQl, g_Ql);
    cudaGetSymbolAddress((void**)&gKh, g_Kh);
    cudaGetSymbolAddress((void**)&gKl, g_Kl);
    cudaGetSymbolAddress((void**)&gVh, g_Vh);
    cudaGetSymbolAddress((void**)&gVl, g_Vl);
    cudaGetSymbolAddress((void**)&gC,  g_C);

    cudaFuncSetAttribute(gemm_mma_kernel,
                         cudaFuncAttributeMaxDynamicSharedMemorySize, GEMM_SMEM);
    cudaFuncSetAttribute(attn_mma_kernel,
                         cudaFuncAttributeMaxDynamicSharedMemorySize, ATT_SMEM);

    mask8_kernel<<<(SEQ * SEQ) / (256 * 4), 256>>>(mask);

    dim3 gemm_grid(D_MODEL / 128, M_TOT / 128);   // (8, 32) = 256 CTAs
    gemm_mma_kernel<<<gemm_grid, 256, GEMM_SMEM>>>(q, wq, bq, nullptr, gQh, gQl);
    gemm_mma_kernel<<<gemm_grid, 256, GEMM_SMEM>>>(k, wk, bk, nullptr, gKh, gKl);
    gemm_mma_kernel<<<gemm_grid, 256, GEMM_SMEM>>>(v, wv, bv, nullptr, gVh, gVl);

    dim3 attn_grid(SEQ / 128, NHEAD, BATCH);      // (16, 16, 2) = 512 CTAs
    attn_mma_kernel<<<attn_grid, 256, ATT_SMEM>>>();

    gemm_mma_kernel<<<gemm_grid, 256, GEMM_SMEM>>>(gC, wo, bo, out, nullptr, nullptr);
}

// round 6
// speedup vs baseline: 3.2436x; 1.1117x over previous
#include <cuda_runtime.h>
#include <cuda_bf16.h>
#include <cstdint>
#include <cstddef>

#define D_MODEL 1024
#define NHEAD   16
#define DK      64
#define BATCH   2
#define SEQ     2048
#define M_TOT   (BATCH * SEQ)                 // 4096
#define NXE     ((size_t)M_TOT * D_MODEL)     // 4M elems
#define NWE     ((size_t)D_MODEL * D_MODEL)   // 1M elems

// Scratch (allocation-free: __device__ globals)
__device__ __nv_bfloat16 g_INh[3 * NXE];   // split q,k,v inputs (hi)
__device__ __nv_bfloat16 g_INl[3 * NXE];   // (lo)
__device__ __nv_bfloat16 g_Wh[4 * NWE];    // split wq,wk,wv,wo (hi)
__device__ __nv_bfloat16 g_Wl[4 * NWE];    // (lo)
__device__ __nv_bfloat16 g_Ph[3 * NXE];    // projected Q,K,V (hi)
__device__ __nv_bfloat16 g_Pl[3 * NXE];    // (lo)
__device__ __nv_bfloat16 g_Ch[NXE];        // attention context (hi)
__device__ __nv_bfloat16 g_Cl[NXE];        // (lo)
__device__ unsigned char g_mask8[(size_t)SEQ * SEQ];

// ===========================================================================
// Helpers (baseline PTX ISA only — compute_103-safe)
// ===========================================================================
__device__ __forceinline__ uint32_t smem_u32(const void* p) {
    uint32_t a;
    asm("{ .reg .u64 t; cvta.to.shared.u64 t, %1; cvt.u32.u64 %0, t; }"
        : "=r"(a) : "l"(p));
    return a;
}

#define LDM4(r, addr) \
    asm volatile("ldmatrix.sync.aligned.m8n8.x4.shared.b16 {%0,%1,%2,%3}, [%4];" \
        : "=r"((r)[0]), "=r"((r)[1]), "=r"((r)[2]), "=r"((r)[3]) : "r"(addr))

#define LDM4_T(r, addr) \
    asm volatile("ldmatrix.sync.aligned.m8n8.x4.trans.shared.b16 {%0,%1,%2,%3}, [%4];" \
        : "=r"((r)[0]), "=r"((r)[1]), "=r"((r)[2]), "=r"((r)[3]) : "r"(addr))

#define MMA_BF16(d, a, b0, b1) \
    asm volatile("mma.sync.aligned.m16n8k16.row.col.f32.bf16.bf16.f32 " \
        "{%0,%1,%2,%3}, {%4,%5,%6,%7}, {%8,%9}, {%0,%1,%2,%3};" \
        : "+f"((d)[0]), "+f"((d)[1]), "+f"((d)[2]), "+f"((d)[3]) \
        : "r"((a)[0]), "r"((a)[1]), "r"((a)[2]), "r"((a)[3]), "r"(b0), "r"(b1))

#define CP16(sa, gp) \
    asm volatile("{ .reg .u64 g; cvta.to.global.u64 g, %1; " \
                 "cp.async.cg.shared.global [%0], [g], 16; }" \
        :: "r"((uint32_t)(sa)), "l"(gp) : "memory")
#define CP_COMMIT  asm volatile("cp.async.commit_group;" ::: "memory")
#define CP_WAIT1   asm volatile("cp.async.wait_group 1;" ::: "memory")
#define CP_WAIT0   asm volatile("cp.async.wait_group 0;" ::: "memory")

__device__ __forceinline__ uint32_t pack_bf16(float a, float b) {
    __nv_bfloat162 h = __floats2bfloat162_rn(a, b);
    return *(uint32_t*)&h;
}
__device__ __forceinline__ uint32_t pack_bf16_lo(float a, float b) {
    float ra = a - __bfloat162float(__float2bfloat16_rn(a));
    float rb = b - __bfloat162float(__float2bfloat16_rn(b));
    return pack_bf16(ra, rb);
}
__device__ __forceinline__ void cvt4_split(float4 f, uint2& hi, uint2& lo) {
    hi.x = pack_bf16(f.x, f.y);    hi.y = pack_bf16(f.z, f.w);
    lo.x = pack_bf16_lo(f.x, f.y); lo.y = pack_bf16_lo(f.z, f.w);
}

// XOR swizzle: 128B rows, 16B chunks permuted within row (ldmatrix-safe)
__device__ __forceinline__ uint32_t swz(uint32_t row, uint32_t chunk) {
    return (row << 7) + ((chunk ^ (row & 7)) << 4);
}

// ===========================================================================
// Pre-pass kernels
// ===========================================================================
__global__ void mask8_kernel(const int* __restrict__ m)
{
    const size_t i = ((size_t)blockIdx.x * 256 + threadIdx.x) << 2;
    int4 v = *(const int4*)(m + i);
    uchar4 o;
    o.x = (unsigned char)v.x; o.y = (unsigned char)v.y;
    o.z = (unsigned char)v.z; o.w = (unsigned char)v.w;
    *(uchar4*)(g_mask8 + i) = o;
}

__global__ void split_qkv_kernel(const float* __restrict__ q,
                                 const float* __restrict__ k,
                                 const float* __restrict__ v)
{
    const int z = blockIdx.z;
    const float* src = (z == 0) ? q : (z == 1) ? k : v;
    const size_t i = ((size_t)blockIdx.x * 256 + threadIdx.x) << 2;
    float4 f = *(const float4*)(src + i);
    uint2 hi, lo; cvt4_split(f, hi, lo);
    *(uint2*)(g_INh + (size_t)z * NXE + i) = hi;
    *(uint2*)(g_INl + (size_t)z * NXE + i) = lo;
}

__global__ void split_w_kernel(const float* __restrict__ w0,
                               const float* __restrict__ w1,
                               const float* __restrict__ w2,
                               const float* __restrict__ w3)
{
    const int z = blockIdx.z;
    const float* src = (z == 0) ? w0 : (z == 1) ? w1 : (z == 2) ? w2 : w3;
    const size_t i = ((size_t)blockIdx.x * 256 + threadIdx.x) << 2;
    float4 f = *(const float4*)(src + i);
    uint2 hi, lo; cvt4_split(f, hi, lo);
    *(uint2*)(g_Wh + (size_t)z * NWE + i) = hi;
    *(uint2*)(g_Wl + (size_t)z * NWE + i) = lo;
}

// ===========================================================================
// GEMM core (pre-split bf16 operands, cp.async 3-stage pipeline)
// CTA tile 128x128, BK=32. smem stage 32K: A(hi|lo packed rows) 16K + B 16K.
// Row layout: 128B = [32 hi bf16 | 32 lo bf16], XOR-swizzled.
// ===========================================================================
#define GSTG      32768
#define GEMM_SMEM (3 * GSTG)   // 98304

__device__ __forceinline__ void gemm_core(
    const __nv_bfloat16* __restrict__ Xh, const __nv_bfloat16* __restrict__ Xl,
    const __nv_bfloat16* __restrict__ Wh, const __nv_bfloat16* __restrict__ Wl,
    uint32_t sb, int m0, int n0, float (&acc)[4][4][4])
{
    const int t    = threadIdx.x;
    const int lane = t & 31;
    const int wid  = t >> 5;
    const int wm   = (wid & 1) << 6;
    const int wn   = (wid >> 1) << 5;

    auto issue = [&](int kt, int s) {
        const uint32_t base = sb + s * GSTG;
        const int k0 = kt << 5;
#pragma unroll
        for (int i = 0; i < 4; i++) {
            const int idx = t + (i << 8);
            const int row = idx >> 3, ch = idx & 7;
            const __nv_bfloat16* px = (ch < 4) ? Xh : Xl;
            const __nv_bfloat16* pw = (ch < 4) ? Wh : Wl;
            const int cc = (ch & 3) << 3;
            const uint32_t so = swz(row, ch);
            CP16(base + so,         px + (size_t)(m0 + row) * D_MODEL + k0 + cc);
            CP16(base + 16384 + so, pw + (size_t)(n0 + row) * D_MODEL + k0 + cc);
        }
    };

    issue(0, 0); CP_COMMIT;
    issue(1, 1); CP_COMMIT;

    for (int kt = 0; kt < 32; kt++) {
        if (kt < 30) { CP_WAIT1; } else { CP_WAIT0; }
        __syncthreads();
        if (kt < 30) { issue(kt + 2, (kt + 2) % 3); CP_COMMIT; }

        const uint32_t abuf = sb + (kt % 3) * GSTG;
        const uint32_t bbuf = abuf + 16384;
#pragma unroll
        for (int ks = 0; ks < 2; ks++) {
            uint32_t bh[4][2], bl[4][2];
#pragma unroll
            for (int p = 0; p < 2; p++) {
                const int nr = wn + (p << 4) + (lane & 7) + ((lane >> 4) << 3);
                const int ch = (ks << 1) + ((lane >> 3) & 1);
                uint32_t qq[4];
                LDM4(qq, bbuf + swz(nr, ch));
                bh[2 * p][0] = qq[0]; bh[2 * p][1] = qq[1];
                bh[2 * p + 1][0] = qq[2]; bh[2 * p + 1][1] = qq[3];
                LDM4(qq, bbuf + swz(nr, ch + 4));
                bl[2 * p][0] = qq[0]; bl[2 * p][1] = qq[1];
                bl[2 * p + 1][0] = qq[2]; bl[2 * p + 1][1] = qq[3];
            }
#pragma unroll
            for (int mi = 0; mi < 4; mi++) {
                const int row = wm + (mi << 4) + (lane & 15);
                const int ch  = (ks << 1) + (lane >> 4);
                uint32_t ah[4], al[4];
                LDM4(ah, abuf + swz(row, ch));
                LDM4(al, abuf + swz(row, ch + 4));
#pragma unroll
                for (int ni = 0; ni < 4; ni++) {
                    MMA_BF16(acc[mi][ni], ah, bh[ni][0], bh[ni][1]);
                    MMA_BF16(acc[mi][ni], ah, bl[ni][0], bl[ni][1]);
                    MMA_BF16(acc[mi][ni], al, bh[ni][0], bh[ni][1]);
                }
            }
        }
    }
}

// ---- batched Q/K/V projections (z = 0,1,2), bf16 hi/lo epilogue ----
__global__ __launch_bounds__(256, 2) void gemm_qkv_kernel(
    const float* __restrict__ bq, const float* __restrict__ bk,
    const float* __restrict__ bv)
{
    extern __shared__ char sm[];
    const uint32_t sb = smem_u32(sm);
    const int z  = blockIdx.z;
    const int m0 = blockIdx.y << 7;
    const int n0 = blockIdx.x << 7;
    const size_t zo = (size_t)z * NXE;

    float acc[4][4][4] = {};
    gemm_core(g_INh + zo, g_INl + zo,
              g_Wh + (size_t)z * NWE, g_Wl + (size_t)z * NWE,
              sb, m0, n0, acc);

    const float* bias = (z == 0) ? bq : (z == 1) ? bk : bv;
    __nv_bfloat16* Yh = g_Ph + zo;
    __nv_bfloat16* Yl = g_Pl + zo;

    const int lane = threadIdx.x & 31;
    const int wid  = threadIdx.x >> 5;
    const int wm   = (wid & 1) << 6;
    const int wn   = (wid >> 1) << 5;
    const int lr4  = lane >> 2;
    const int lc2  = (lane & 3) << 1;
#pragma unroll
    for (int mi = 0; mi < 4; mi++) {
        const int r = m0 + wm + (mi << 4) + lr4;
#pragma unroll
        for (int ni = 0; ni < 4; ni++) {
            const int c = n0 + wn + (ni << 3) + lc2;
            const float bx = bias[c], by = bias[c + 1];
            const float v0 = acc[mi][ni][0] + bx, v1 = acc[mi][ni][1] + by;
            const float v2 = acc[mi][ni][2] + bx, v3 = acc[mi][ni][3] + by;
            *(uint32_t*)(Yh + (size_t)r * D_MODEL + c)       = pack_bf16(v0, v1);
            *(uint32_t*)(Yl + (size_t)r * D_MODEL + c)       = pack_bf16_lo(v0, v1);
            *(uint32_t*)(Yh + (size_t)(r + 8) * D_MODEL + c) = pack_bf16(v2, v3);
            *(uint32_t*)(Yl + (size_t)(r + 8) * D_MODEL + c) = pack_bf16_lo(v2, v3);
        }
    }
}

// ---- output projection, fp32 epilogue ----
__global__ __launch_bounds__(256, 2) void gemm_out_kernel(
    const float* __restrict__ bo, float* __restrict__ out)
{
    extern __shared__ char sm[];
    const uint32_t sb = smem_u32(sm);
    const int m0 = blockIdx.y << 7;
    const int n0 = blockIdx.x << 7;

    float acc[4][4][4] = {};
    gemm_core(g_Ch, g_Cl, g_Wh + 3 * NWE, g_Wl + 3 * NWE, sb, m0, n0, acc);

    const int lane = threadIdx.x & 31;
    const int wid  = threadIdx.x >> 5;
    const int wm   = (wid & 1) << 6;
    const int wn   = (wid >> 1) << 5;
    const int lr4  = lane >> 2;
    const int lc2  = (lane & 3) << 1;
#pragma unroll
    for (int mi = 0; mi < 4; mi++) {
        const int r = m0 + wm + (mi << 4) + lr4;
#pragma unroll
        for (int ni = 0; ni < 4; ni++) {
            const int c = n0 + wn + (ni << 3) + lc2;
            const float bx = bo[c], by = bo[c + 1];
            float2 o0, o1;
            o0.x = acc[mi][ni][0] + bx; o0.y = acc[mi][ni][1] + by;
            o1.x = acc[mi][ni][2] + bx; o1.y = acc[mi][ni][3] + by;
            *(float2*)(out + (size_t)r * D_MODEL + c)       = o0;
            *(float2*)(out + (size_t)(r + 8) * D_MODEL + c) = o1;
        }
    }
}

// ===========================================================================
// Tensor-core flash attention (round-5 proven; sources = g_Ph/g_Pl planes,
// context written directly as bf16 hi/lo planes).
// smem: Qh 16K | Ql 16K | 2 x stage(Kh 8K, Kl 8K, Vh 8K, Vl 8K) = 96 KB
// ===========================================================================
#define AS_QLO   16384
#define AS_STG   32768
#define AS_STGSZ 32768
#define AS_KLO   8192
#define AS_VHI   16384
#define AS_VLO   24576
#define ATT_SMEM 98304

__global__ __launch_bounds__(256, 2) void attn_mma_kernel()
{
    extern __shared__ char sm[];
    const uint32_t sb = smem_u32(sm);
    const int t    = threadIdx.x;
    const int lane = t & 31;
    const int w    = t >> 5;
    const int b  = blockIdx.z;
    const int h  = blockIdx.y;
    const int q0 = blockIdx.x << 7;
    const size_t bS   = (size_t)b * SEQ;
    const size_t hoff = (size_t)h * DK;

    const __nv_bfloat16* Qh = g_Ph;
    const __nv_bfloat16* Ql = g_Pl;
    const __nv_bfloat16* Kh = g_Ph + NXE;
    const __nv_bfloat16* Kl = g_Pl + NXE;
    const __nv_bfloat16* Vh = g_Ph + 2 * NXE;
    const __nv_bfloat16* Vl = g_Pl + 2 * NXE;

    auto issue_stage = [&](int kt, int bufsel) {
        const uint32_t base = sb + AS_STG + bufsel * AS_STGSZ;
#pragma unroll
        for (int i = 0; i < 2; i++) {
            const int idx = t + (i << 8);
            const int row = idx >> 3, ch = idx & 7;
            const size_t go = (bS + (kt << 6) + row) * D_MODEL + hoff + (ch << 3);
            const uint32_t so = swz(row, ch);
            CP16(base + so,          Kh + go);
            CP16(base + AS_KLO + so, Kl + go);
            CP16(base + AS_VHI + so, Vh + go);
            CP16(base + AS_VLO + so, Vl + go);
        }
    };

#pragma unroll
    for (int i = 0; i < 4; i++) {
        const int idx = t + (i << 8);
        const int row = idx >> 3, ch = idx & 7;
        const size_t go = (bS + q0 + row) * D_MODEL + hoff + (ch << 3);
        const uint32_t so = swz(row, ch);
        CP16(sb + so,          Qh + go);
        CP16(sb + AS_QLO + so, Ql + go);
    }
    issue_stage(0, 0);
    CP_COMMIT;
    issue_stage(1, 1);
    CP_COMMIT;
    CP_WAIT1;
    __syncthreads();

    float O[8][4] = {};
    float m0 = -1e30f, m1 = -1e30f, l0 = 0.0f, l1 = 0.0f;

    const int qr = q0 + (w << 4) + (lane >> 2);
    const int kc = (lane & 3) << 1;

    for (int kt = 0; kt < SEQ / 64; kt++) {
        const uint32_t kb = sb + AS_STG + (kt & 1) * AS_STGSZ;

        // ---- S = Q . K^T ----
        float S[8][4] = {};
#pragma unroll
        for (int ks = 0; ks < 4; ks++) {
            uint32_t qh[4], ql[4];
            {
                const int row = (w << 4) + (lane & 15);
                const int ch  = (ks << 1) + (lane >> 4);
                const uint32_t qa = sb + swz(row, ch);
                LDM4(qh, qa);
                LDM4(ql, qa + AS_QLO);
            }
#pragma unroll
            for (int g = 0; g < 4; g++) {
                const int nr = (g << 4) + (lane & 7) + ((lane >> 4) << 3);
                const int ch = (ks << 1) + ((lane >> 3) & 1);
                const uint32_t ka = kb + swz(nr, ch);
                uint32_t kh[4], kl[4];
                LDM4(kh, ka);
                LDM4(kl, ka + AS_KLO);
                MMA_BF16(S[2 * g],     qh, kh[0], kh[1]);
                MMA_BF16(S[2 * g],     qh, kl[0], kl[1]);
                MMA_BF16(S[2 * g],     ql, kh[0], kh[1]);
                MMA_BF16(S[2 * g + 1], qh, kh[2], kh[3]);
                MMA_BF16(S[2 * g + 1], qh, kl[2], kl[3]);
                MMA_BF16(S[2 * g + 1], ql, kh[2], kh[3]);
            }
        }

        // ---- scale + soft mask (u8) ----
        const unsigned char* mp0 = g_mask8 + (size_t)qr * SEQ + (kt << 6) + kc;
        const unsigned char* mp1 = mp0 + (size_t)8 * SEQ;
#pragma unroll
        for (int j = 0; j < 8; j++) {
            const unsigned short k0v = *(const unsigned short*)(mp0 + (j << 3));
            const unsigned short k1v = *(const unsigned short*)(mp1 + (j << 3));
            S[j][0] = (k0v & 0xff) ? S[j][0] * 0.125f : -1.0f;
            S[j][1] = (k0v >> 8)   ? S[j][1] * 0.125f : -1.0f;
            S[j][2] = (k1v & 0xff) ? S[j][2] * 0.125f : -1.0f;
            S[j][3] = (k1v >> 8)   ? S[j][3] * 0.125f : -1.0f;
        }

        // ---- online softmax ----
        float tm0 = -1e30f, tm1 = -1e30f;
#pragma unroll
        for (int j = 0; j < 8; j++) {
            tm0 = fmaxf(tm0, fmaxf(S[j][0], S[j][1]));
            tm1 = fmaxf(tm1, fmaxf(S[j][2], S[j][3]));
        }
        tm0 = fmaxf(tm0, __shfl_xor_sync(0xffffffffu, tm0, 1));
        tm0 = fmaxf(tm0, __shfl_xor_sync(0xffffffffu, tm0, 2));
        tm1 = fmaxf(tm1, __shfl_xor_sync(0xffffffffu, tm1, 1));
        tm1 = fmaxf(tm1, __shfl_xor_sync(0xffffffffu, tm1, 2));
        const float mn0 = fmaxf(m0, tm0);
        const float mn1 = fmaxf(m1, tm1);
        const float a0 = __expf(m0 - mn0);
        const float a1 = __expf(m1 - mn1);
        float rs0 = 0.0f, rs1 = 0.0f;
#pragma unroll
        for (int j = 0; j < 8; j++) {
            S[j][0] = __expf(S[j][0] - mn0);
            S[j][1] = __expf(S[j][1] - mn0);
            S[j][2] = __expf(S[j][2] - mn1);
            S[j][3] = __expf(S[j][3] - mn1);
            rs0 += S[j][0] + S[j][1];
            rs1 += S[j][2] + S[j][3];
        }
        rs0 += __shfl_xor_sync(0xffffffffu, rs0, 1);
        rs0 += __shfl_xor_sync(0xffffffffu, rs0, 2);
        rs1 += __shfl_xor_sync(0xffffffffu, rs1, 1);
        rs1 += __shfl_xor_sync(0xffffffffu, rs1, 2);
        l0 = l0 * a0 + rs0;
        l1 = l1 * a1 + rs1;
        m0 = mn0; m1 = mn1;
#pragma unroll
        for (int j = 0; j < 8; j++) {
            O[j][0] *= a0; O[j][1] *= a0;
            O[j][2] *= a1; O[j][3] *= a1;
        }

        // ---- re-pack P into bf16 hi/lo A-frags ----
        uint32_t Ph[4][4], Pl[4][4];
#pragma unroll
        for (int tt = 0; tt < 4; tt++) {
            const float* p0 = S[2 * tt];
            const float* p1 = S[2 * tt + 1];
            Ph[tt][0] = pack_bf16(p0[0], p0[1]);
            Ph[tt][1] = pack_bf16(p0[2], p0[3]);
            Ph[tt][2] = pack_bf16(p1[0], p1[1]);
            Ph[tt][3] = pack_bf16(p1[2], p1[3]);
            Pl[tt][0] = pack_bf16_lo(p0[0], p0[1]);
            Pl[tt][1] = pack_bf16_lo(p0[2], p0[3]);
            Pl[tt][2] = pack_bf16_lo(p1[0], p1[1]);
            Pl[tt][3] = pack_bf16_lo(p1[2], p1[3]);
        }

        // ---- O += P . V ----
#pragma unroll
        for (int tt = 0; tt < 4; tt++) {
#pragma unroll
            for (int g = 0; g < 4; g++) {
                const int row = (tt << 4) + (lane & 15);
                const int ch  = (g << 1) + (lane >> 4);
                const uint32_t va = kb + AS_VHI + swz(row, ch);
                uint32_t vh[4], vl[4];
                LDM4_T(vh, va);
                LDM4_T(vl, va + 8192);
                MMA_BF16(O[2 * g],     Ph[tt], vh[0], vh[1]);
                MMA_BF16(O[2 * g],     Ph[tt], vl[0], vl[1]);
                MMA_BF16(O[2 * g],     Pl[tt], vh[0], vh[1]);
                MMA_BF16(O[2 * g + 1], Ph[tt], vh[2], vh[3]);
                MMA_BF16(O[2 * g + 1], Ph[tt], vl[2], vl[3]);
                MMA_BF16(O[2 * g + 1], Pl[tt], vh[2], vh[3]);
            }
        }

        // ---- pipeline advance ----
        if (kt < 30) {
            __syncthreads();
            issue_stage(kt + 2, kt & 1);
            CP_COMMIT;
            CP_WAIT1;
            __syncthreads();
        } else if (kt == 30) {
            CP_WAIT0;
            __syncthreads();
        }
    }

    // ---- normalize + write context as bf16 hi/lo planes [B,S,H*DK] ----
    const float i0 = 1.0f / l0;
    const float i1 = 1.0f / l1;
    const size_t co0 = (bS + qr) * D_MODEL + hoff + kc;
    const size_t co1 = co0 + (size_t)8 * D_MODEL;
#pragma unroll
    for (int j = 0; j < 8; j++) {
        const float v0 = O[j][0] * i0, v1 = O[j][1] * i0;
        const float v2 = O[j][2] * i1, v3 = O[j][3] * i1;
        *(uint32_t*)(g_Ch + co0 + (j << 3)) = pack_bf16(v0, v1);
        *(uint32_t*)(g_Cl + co0 + (j << 3)) = pack_bf16_lo(v0, v1);
        *(uint32_t*)(g_Ch + co1 + (j << 3)) = pack_bf16(v2, v3);
        *(uint32_t*)(g_Cl + co1 + (j << 3)) = pack_bf16_lo(v2, v3);
    }
}

// ---------------------------------------------------------------------------
extern "C" void kernel_launch(void* const* d_in, const int* in_sizes, int n_in,
                              void* d_out, int out_size)
{
    const float* q    = (const float*)d_in[0];
    const float* k    = (const float*)d_in[1];
    const float* v    = (const float*)d_in[2];
    const int*   mask = (const int*)  d_in[3];
    const float* wq   = (const float*)d_in[4];
    const float* bq   = (const float*)d_in[5];
    const float* wk   = (const float*)d_in[6];
    const float* bk   = (const float*)d_in[7];
    const float* wv   = (const float*)d_in[8];
    const float* bv   = (const float*)d_in[9];
    const float* wo   = (const float*)d_in[10];
    const float* bo   = (const float*)d_in[11];
    float* out = (float*)d_out;

    cudaFuncSetAttribute(gemm_qkv_kernel,
                         cudaFuncAttributeMaxDynamicSharedMemorySize, GEMM_SMEM);
    cudaFuncSetAttribute(gemm_out_kernel,
                         cudaFuncAttributeMaxDynamicSharedMemorySize, GEMM_SMEM);
    cudaFuncSetAttribute(attn_mma_kernel,
                         cudaFuncAttributeMaxDynamicSharedMemorySize, ATT_SMEM);

    mask8_kernel<<<(SEQ * SEQ) / (256 * 4), 256>>>(mask);
    split_qkv_kernel<<<dim3(NXE / 1024, 1, 3), 256>>>(q, k, v);
    split_w_kernel<<<dim3(NWE / 1024, 1, 4), 256>>>(wq, wk, wv, wo);

    gemm_qkv_kernel<<<dim3(8, 32, 3), 256, GEMM_SMEM>>>(bq, bk, bv);

    attn_mma_kernel<<<dim3(SEQ / 128, NHEAD, BATCH), 256, ATT_SMEM>>>();

    gemm_out_kernel<<<dim3(8, 32, 1), 256, GEMM_SMEM>>>(bo, out);
}

// round 7
// speedup vs baseline: 3.2803x; 1.0113x over previous
#include <cuda_runtime.h>
#include <cuda_bf16.h>
#include <cstdint>
#include <cstddef>

#define D_MODEL 1024
#define NHEAD   16
#define DK      64
#define BATCH   2
#define SEQ     2048
#define M_TOT   (BATCH * SEQ)                 // 4096
#define NXE     ((size_t)M_TOT * D_MODEL)     // 4M elems
#define NWE     ((size_t)D_MODEL * D_MODEL)   // 1M elems

// Scratch (allocation-free: __device__ globals)
__device__ __nv_bfloat16 g_INh[3 * NXE];   // split q,k,v inputs (hi)
__device__ __nv_bfloat16 g_INl[3 * NXE];   // (lo)
__device__ __nv_bfloat16 g_Wh[4 * NWE];    // split wq,wk,wv,wo (hi)
__device__ __nv_bfloat16 g_Wl[4 * NWE];    // (lo)
__device__ __nv_bfloat16 g_Ph[3 * NXE];    // projected Q,K,V (hi)
__device__ __nv_bfloat16 g_Pl[3 * NXE];    // (lo)
__device__ __nv_bfloat16 g_Ch[NXE];        // attention context (hi)
__device__ __nv_bfloat16 g_Cl[NXE];        // (lo)
__device__ unsigned char g_mask8[(size_t)SEQ * SEQ];

// ===========================================================================
// Helpers (baseline PTX ISA only — compute_103-safe)
// ===========================================================================
__device__ __forceinline__ uint32_t smem_u32(const void* p) {
    uint32_t a;
    asm("{ .reg .u64 t; cvta.to.shared.u64 t, %1; cvt.u32.u64 %0, t; }"
        : "=r"(a) : "l"(p));
    return a;
}

#define LDM4(r, addr) \
    asm volatile("ldmatrix.sync.aligned.m8n8.x4.shared.b16 {%0,%1,%2,%3}, [%4];" \
        : "=r"((r)[0]), "=r"((r)[1]), "=r"((r)[2]), "=r"((r)[3]) : "r"(addr))

#define LDM4_T(r, addr) \
    asm volatile("ldmatrix.sync.aligned.m8n8.x4.trans.shared.b16 {%0,%1,%2,%3}, [%4];" \
        : "=r"((r)[0]), "=r"((r)[1]), "=r"((r)[2]), "=r"((r)[3]) : "r"(addr))

#define MMA_BF16(d, a, b0, b1) \
    asm volatile("mma.sync.aligned.m16n8k16.row.col.f32.bf16.bf16.f32 " \
        "{%0,%1,%2,%3}, {%4,%5,%6,%7}, {%8,%9}, {%0,%1,%2,%3};" \
        : "+f"((d)[0]), "+f"((d)[1]), "+f"((d)[2]), "+f"((d)[3]) \
        : "r"((a)[0]), "r"((a)[1]), "r"((a)[2]), "r"((a)[3]), "r"(b0), "r"(b1))

#define CP16(sa, gp) \
    asm volatile("{ .reg .u64 g; cvta.to.global.u64 g, %1; " \
                 "cp.async.cg.shared.global [%0], [g], 16; }" \
        :: "r"((uint32_t)(sa)), "l"(gp) : "memory")
#define CP_COMMIT  asm volatile("cp.async.commit_group;" ::: "memory")
#define CP_WAIT1   asm volatile("cp.async.wait_group 1;" ::: "memory")
#define CP_WAIT0   asm volatile("cp.async.wait_group 0;" ::: "memory")

__device__ __forceinline__ uint32_t pack_bf16(float a, float b) {
    __nv_bfloat162 h = __floats2bfloat162_rn(a, b);
    return *(uint32_t*)&h;
}
// Truncation split: hi = top 16 bits of fp32 (exact bf16), lo = exact residual
// rounded to bf16. Dropped hi-rounding vs rn costs nothing extra downstream
// because lo absorbs the full residual. 1 PRMT for the hi pair.
__device__ __forceinline__ uint32_t pack2_hi_trunc(float a, float b) {
    return __byte_perm(__float_as_uint(a), __float_as_uint(b), 0x7632);
}
__device__ __forceinline__ uint32_t pack2_lo_trunc(float a, float b) {
    float ah = __uint_as_float(__float_as_uint(a) & 0xFFFF0000u);
    float bh = __uint_as_float(__float_as_uint(b) & 0xFFFF0000u);
    return pack_bf16(a - ah, b - bh);
}
__device__ __forceinline__ void cvt4_split(float4 f, uint2& hi, uint2& lo) {
    hi.x = pack2_hi_trunc(f.x, f.y);  hi.y = pack2_hi_trunc(f.z, f.w);
    lo.x = pack2_lo_trunc(f.x, f.y);  lo.y = pack2_lo_trunc(f.z, f.w);
}

// XOR swizzle: 128B rows, 16B chunks permuted within row (ldmatrix-safe)
__device__ __forceinline__ uint32_t swz(uint32_t row, uint32_t chunk) {
    return (row << 7) + ((chunk ^ (row & 7)) << 4);
}

// ===========================================================================
// Pre-pass kernels
// ===========================================================================
__global__ void mask8_kernel(const int* __restrict__ m)
{
    const size_t i = ((size_t)blockIdx.x * 256 + threadIdx.x) << 2;
    int4 v = *(const int4*)(m + i);
    uchar4 o;
    o.x = (unsigned char)v.x; o.y = (unsigned char)v.y;
    o.z = (unsigned char)v.z; o.w = (unsigned char)v.w;
    *(uchar4*)(g_mask8 + i) = o;
}

__global__ void split_qkv_kernel(const float* __restrict__ q,
                                 const float* __restrict__ k,
                                 const float* __restrict__ v)
{
    const int z = blockIdx.z;
    const float* src = (z == 0) ? q : (z == 1) ? k : v;
    const size_t i = ((size_t)blockIdx.x * 256 + threadIdx.x) << 2;
    float4 f = *(const float4*)(src + i);
    uint2 hi, lo; cvt4_split(f, hi, lo);
    *(uint2*)(g_INh + (size_t)z * NXE + i) = hi;
    *(uint2*)(g_INl + (size_t)z * NXE + i) = lo;
}

__global__ void split_w_kernel(const float* __restrict__ w0,
                               const float* __restrict__ w1,
                               const float* __restrict__ w2,
                               const float* __restrict__ w3)
{
    const int z = blockIdx.z;
    const float* src = (z == 0) ? w0 : (z == 1) ? w1 : (z == 2) ? w2 : w3;
    const size_t i = ((size_t)blockIdx.x * 256 + threadIdx.x) << 2;
    float4 f = *(const float4*)(src + i);
    uint2 hi, lo; cvt4_split(f, hi, lo);
    *(uint2*)(g_Wh + (size_t)z * NWE + i) = hi;
    *(uint2*)(g_Wl + (size_t)z * NWE + i) = lo;
}

// ===========================================================================
// GEMM core (pre-split bf16 operands, cp.async 3-stage pipeline)
// CTA tile 128x128, BK=32. smem stage 32K: A(hi|lo packed rows) 16K + B 16K.
// Row layout: 128B = [32 hi bf16 | 32 lo bf16], XOR-swizzled.
// ===========================================================================
#define GSTG      32768
#define GEMM_SMEM (3 * GSTG)   // 98304

__device__ __forceinline__ void gemm_core(
    const __nv_bfloat16* __restrict__ Xh, const __nv_bfloat16* __restrict__ Xl,
    const __nv_bfloat16* __restrict__ Wh, const __nv_bfloat16* __restrict__ Wl,
    uint32_t sb, int m0, int n0, float (&acc)[4][4][4])
{
    const int t    = threadIdx.x;
    const int lane = t & 31;
    const int wid  = t >> 5;
    const int wm   = (wid & 1) << 6;
    const int wn   = (wid >> 1) << 5;

    auto issue = [&](int kt, int s) {
        const uint32_t base = sb + s * GSTG;
        const int k0 = kt << 5;
#pragma unroll
        for (int i = 0; i < 4; i++) {
            const int idx = t + (i << 8);
            const int row = idx >> 3, ch = idx & 7;
            const __nv_bfloat16* px = (ch < 4) ? Xh : Xl;
            const __nv_bfloat16* pw = (ch < 4) ? Wh : Wl;
            const int cc = (ch & 3) << 3;
            const uint32_t so = swz(row, ch);
            CP16(base + so,         px + (size_t)(m0 + row) * D_MODEL + k0 + cc);
            CP16(base + 16384 + so, pw + (size_t)(n0 + row) * D_MODEL + k0 + cc);
        }
    };

    issue(0, 0); CP_COMMIT;
    issue(1, 1); CP_COMMIT;

    for (int kt = 0; kt < 32; kt++) {
        if (kt < 30) { CP_WAIT1; } else { CP_WAIT0; }
        __syncthreads();
        if (kt < 30) { issue(kt + 2, (kt + 2) % 3); CP_COMMIT; }

        const uint32_t abuf = sb + (kt % 3) * GSTG;
        const uint32_t bbuf = abuf + 16384;
#pragma unroll
        for (int ks = 0; ks < 2; ks++) {
            uint32_t bh[4][2], bl[4][2];
#pragma unroll
            for (int p = 0; p < 2; p++) {
                const int nr = wn + (p << 4) + (lane & 7) + ((lane >> 4) << 3);
                const int ch = (ks << 1) + ((lane >> 3) & 1);
                uint32_t qq[4];
                LDM4(qq, bbuf + swz(nr, ch));
                bh[2 * p][0] = qq[0]; bh[2 * p][1] = qq[1];
                bh[2 * p + 1][0] = qq[2]; bh[2 * p + 1][1] = qq[3];
                LDM4(qq, bbuf + swz(nr, ch + 4));
                bl[2 * p][0] = qq[0]; bl[2 * p][1] = qq[1];
                bl[2 * p + 1][0] = qq[2]; bl[2 * p + 1][1] = qq[3];
            }
#pragma unroll
            for (int mi = 0; mi < 4; mi++) {
                const int row = wm + (mi << 4) + (lane & 15);
                const int ch  = (ks << 1) + (lane >> 4);
                uint32_t ah[4], al[4];
                LDM4(ah, abuf + swz(row, ch));
                LDM4(al, abuf + swz(row, ch + 4));
#pragma unroll
                for (int ni = 0; ni < 4; ni++) {
                    MMA_BF16(acc[mi][ni], ah, bh[ni][0], bh[ni][1]);
                    MMA_BF16(acc[mi][ni], ah, bl[ni][0], bl[ni][1]);
                    MMA_BF16(acc[mi][ni], al, bh[ni][0], bh[ni][1]);
                }
            }
        }
    }
}

// ---- batched Q/K/V projections (z = 0,1,2), bf16 hi/lo epilogue.
//      Q (z==0) is pre-scaled by 1/sqrt(DK) = 0.125 so attention needs no
//      per-score multiply. ----
__global__ __launch_bounds__(256, 2) void gemm_qkv_kernel(
    const float* __restrict__ bq, const float* __restrict__ bk,
    const float* __restrict__ bv)
{
    extern __shared__ char sm[];
    const uint32_t sb = smem_u32(sm);
    const int z  = blockIdx.z;
    const int m0 = blockIdx.y << 7;
    const int n0 = blockIdx.x << 7;
    const size_t zo = (size_t)z * NXE;

    float acc[4][4][4] = {};
    gemm_core(g_INh + zo, g_INl + zo,
              g_Wh + (size_t)z * NWE, g_Wl + (size_t)z * NWE,
              sb, m0, n0, acc);

    const float* bias = (z == 0) ? bq : (z == 1) ? bk : bv;
    const float sc = (z == 0) ? 0.125f : 1.0f;
    __nv_bfloat16* Yh = g_Ph + zo;
    __nv_bfloat16* Yl = g_Pl + zo;

    const int lane = threadIdx.x & 31;
    const int wid  = threadIdx.x >> 5;
    const int wm   = (wid & 1) << 6;
    const int wn   = (wid >> 1) << 5;
    const int lr4  = lane >> 2;
    const int lc2  = (lane & 3) << 1;
#pragma unroll
    for (int mi = 0; mi < 4; mi++) {
        const int r = m0 + wm + (mi << 4) + lr4;
#pragma unroll
        for (int ni = 0; ni < 4; ni++) {
            const int c = n0 + wn + (ni << 3) + lc2;
            const float bx = bias[c], by = bias[c + 1];
            const float v0 = (acc[mi][ni][0] + bx) * sc, v1 = (acc[mi][ni][1] + by) * sc;
            const float v2 = (acc[mi][ni][2] + bx) * sc, v3 = (acc[mi][ni][3] + by) * sc;
            *(uint32_t*)(Yh + (size_t)r * D_MODEL + c)       = pack2_hi_trunc(v0, v1);
            *(uint32_t*)(Yl + (size_t)r * D_MODEL + c)       = pack2_lo_trunc(v0, v1);
            *(uint32_t*)(Yh + (size_t)(r + 8) * D_MODEL + c) = pack2_hi_trunc(v2, v3);
            *(uint32_t*)(Yl + (size_t)(r + 8) * D_MODEL + c) = pack2_lo_trunc(v2, v3);
        }
    }
}

// ---- output projection, fp32 epilogue ----
__global__ __launch_bounds__(256, 2) void gemm_out_kernel(
    const float* __restrict__ bo, float* __restrict__ out)
{
    extern __shared__ char sm[];
    const uint32_t sb = smem_u32(sm);
    const int m0 = blockIdx.y << 7;
    const int n0 = blockIdx.x << 7;

    float acc[4][4][4] = {};
    gemm_core(g_Ch, g_Cl, g_Wh + 3 * NWE, g_Wl + 3 * NWE, sb, m0, n0, acc);

    const int lane = threadIdx.x & 31;
    const int wid  = threadIdx.x >> 5;
    const int wm   = (wid & 1) << 6;
    const int wn   = (wid >> 1) << 5;
    const int lr4  = lane >> 2;
    const int lc2  = (lane & 3) << 1;
#pragma unroll
    for (int mi = 0; mi < 4; mi++) {
        const int r = m0 + wm + (mi << 4) + lr4;
#pragma unroll
        for (int ni = 0; ni < 4; ni++) {
            const int c = n0 + wn + (ni << 3) + lc2;
            const float bx = bo[c], by = bo[c + 1];
            float2 o0, o1;
            o0.x = acc[mi][ni][0] + bx; o0.y = acc[mi][ni][1] + by;
            o1.x = acc[mi][ni][2] + bx; o1.y = acc[mi][ni][3] + by;
            *(float2*)(out + (size_t)r * D_MODEL + c)       = o0;
            *(float2*)(out + (size_t)(r + 8) * D_MODEL + c) = o1;
        }
    }
}

// ===========================================================================
// Tensor-core flash attention: pre-split, pre-scaled Q/K/V planes.
// Mask u16 loads prefetched BEFORE the QK MMA block (latency off the softmax
// critical path); P re-pack via truncation split (PRMT + exact residual).
// smem: Qh 16K | Ql 16K | 2 x stage(Kh 8K, Kl 8K, Vh 8K, Vl 8K) = 96 KB
// ===========================================================================
#define AS_QLO   16384
#define AS_STG   32768
#define AS_STGSZ 32768
#define AS_KLO   8192
#define AS_VHI   16384
#define AS_VLO   24576
#define ATT_SMEM 98304

__global__ __launch_bounds__(256, 2) void attn_mma_kernel()
{
    extern __shared__ char sm[];
    const uint32_t sb = smem_u32(sm);
    const int t    = threadIdx.x;
    const int lane = t & 31;
    const int w    = t >> 5;
    const int b  = blockIdx.z;
    const int h  = blockIdx.y;
    const int q0 = blockIdx.x << 7;
    const size_t bS   = (size_t)b * SEQ;
    const size_t hoff = (size_t)h * DK;

    const __nv_bfloat16* Qh = g_Ph;
    const __nv_bfloat16* Ql = g_Pl;
    const __nv_bfloat16* Kh = g_Ph + NXE;
    const __nv_bfloat16* Kl = g_Pl + NXE;
    const __nv_bfloat16* Vh = g_Ph + 2 * NXE;
    const __nv_bfloat16* Vl = g_Pl + 2 * NXE;

    auto issue_stage = [&](int kt, int bufsel) {
        const uint32_t base = sb + AS_STG + bufsel * AS_STGSZ;
#pragma unroll
        for (int i = 0; i < 2; i++) {
            const int idx = t + (i << 8);
            const int row = idx >> 3, ch = idx & 7;
            const size_t go = (bS + (kt << 6) + row) * D_MODEL + hoff + (ch << 3);
            const uint32_t so = swz(row, ch);
            CP16(base + so,          Kh + go);
            CP16(base + AS_KLO + so, Kl + go);
            CP16(base + AS_VHI + so, Vh + go);
            CP16(base + AS_VLO + so, Vl + go);
        }
    };

#pragma unroll
    for (int i = 0; i < 4; i++) {
        const int idx = t + (i << 8);
        const int row = idx >> 3, ch = idx & 7;
        const size_t go = (bS + q0 + row) * D_MODEL + hoff + (ch << 3);
        const uint32_t so = swz(row, ch);
        CP16(sb + so,          Qh + go);
        CP16(sb + AS_QLO + so, Ql + go);
    }
    issue_stage(0, 0);
    CP_COMMIT;
    issue_stage(1, 1);
    CP_COMMIT;
    CP_WAIT1;
    __syncthreads();

    float O[8][4] = {};
    float m0 = -1e30f, m1 = -1e30f, l0 = 0.0f, l1 = 0.0f;

    const int qr = q0 + (w << 4) + (lane >> 2);
    const int kc = (lane & 3) << 1;

    for (int kt = 0; kt < SEQ / 64; kt++) {
        const uint32_t kb = sb + AS_STG + (kt & 1) * AS_STGSZ;

        // ---- mask prefetch (global latency hidden behind the QK MMAs) ----
        const unsigned char* mp0 = g_mask8 + (size_t)qr * SEQ + (kt << 6) + kc;
        const unsigned char* mp1 = mp0 + (size_t)8 * SEQ;
        unsigned short mk0[8], mk1[8];
#pragma unroll
        for (int j = 0; j < 8; j++) {
            mk0[j] = *(const unsigned short*)(mp0 + (j << 3));
            mk1[j] = *(const unsigned short*)(mp1 + (j << 3));
        }

        // ---- S = Q . K^T  (Q pre-scaled by 0.125) ----
        float S[8][4] = {};
#pragma unroll
        for (int ks = 0; ks < 4; ks++) {
            uint32_t qh[4], ql[4];
            {
                const int row = (w << 4) + (lane & 15);
                const int ch  = (ks << 1) + (lane >> 4);
                const uint32_t qa = sb + swz(row, ch);
                LDM4(qh, qa);
                LDM4(ql, qa + AS_QLO);
            }
#pragma unroll
            for (int g = 0; g < 4; g++) {
                const int nr = (g << 4) + (lane & 7) + ((lane >> 4) << 3);
                const int ch = (ks << 1) + ((lane >> 3) & 1);
                const uint32_t ka = kb + swz(nr, ch);
                uint32_t kh[4], kl[4];
                LDM4(kh, ka);
                LDM4(kl, ka + AS_KLO);
                MMA_BF16(S[2 * g],     qh, kh[0], kh[1]);
                MMA_BF16(S[2 * g],     qh, kl[0], kl[1]);
                MMA_BF16(S[2 * g],     ql, kh[0], kh[1]);
                MMA_BF16(S[2 * g + 1], qh, kh[2], kh[3]);
                MMA_BF16(S[2 * g + 1], qh, kl[2], kl[3]);
                MMA_BF16(S[2 * g + 1], ql, kh[2], kh[3]);
            }
        }

        // ---- soft mask (select only; scale already folded into Q) ----
#pragma unroll
        for (int j = 0; j < 8; j++) {
            S[j][0] = (mk0[j] & 0xff) ? S[j][0] : -1.0f;
            S[j][1] = (mk0[j] >> 8)   ? S[j][1] : -1.0f;
            S[j][2] = (mk1[j] & 0xff) ? S[j][2] : -1.0f;
            S[j][3] = (mk1[j] >> 8)   ? S[j][3] : -1.0f;
        }

        // ---- online softmax ----
        float tm0 = -1e30f, tm1 = -1e30f;
#pragma unroll
        for (int j = 0; j < 8; j++) {
            tm0 = fmaxf(tm0, fmaxf(S[j][0], S[j][1]));
            tm1 = fmaxf(tm1, fmaxf(S[j][2], S[j][3]));
        }
        tm0 = fmaxf(tm0, __shfl_xor_sync(0xffffffffu, tm0, 1));
        tm0 = fmaxf(tm0, __shfl_xor_sync(0xffffffffu, tm0, 2));
        tm1 = fmaxf(tm1, __shfl_xor_sync(0xffffffffu, tm1, 1));
        tm1 = fmaxf(tm1, __shfl_xor_sync(0xffffffffu, tm1, 2));
        const float mn0 = fmaxf(m0, tm0);
        const float mn1 = fmaxf(m1, tm1);
        const float a0 = __expf(m0 - mn0);
        const float a1 = __expf(m1 - mn1);
        float rs0 = 0.0f, rs1 = 0.0f;
#pragma unroll
        for (int j = 0; j < 8; j++) {
            S[j][0] = __expf(S[j][0] - mn0);
            S[j][1] = __expf(S[j][1] - mn0);
            S[j][2] = __expf(S[j][2] - mn1);
            S[j][3] = __expf(S[j][3] - mn1);
            rs0 += S[j][0] + S[j][1];
            rs1 += S[j][2] + S[j][3];
        }
        rs0 += __shfl_xor_sync(0xffffffffu, rs0, 1);
        rs0 += __shfl_xor_sync(0xffffffffu, rs0, 2);
        rs1 += __shfl_xor_sync(0xffffffffu, rs1, 1);
        rs1 += __shfl_xor_sync(0xffffffffu, rs1, 2);
        l0 = l0 * a0 + rs0;
        l1 = l1 * a1 + rs1;
        m0 = mn0; m1 = mn1;
#pragma unroll
        for (int j = 0; j < 8; j++) {
            O[j][0] *= a0; O[j][1] *= a0;
            O[j][2] *= a1; O[j][3] *= a1;
        }

        // ---- re-pack P into bf16 hi/lo A-frags (truncation split) ----
        uint32_t Ph[4][4], Pl[4][4];
#pragma unroll
        for (int tt = 0; tt < 4; tt++) {
            const float* p0 = S[2 * tt];
            const float* p1 = S[2 * tt + 1];
            Ph[tt][0] = pack2_hi_trunc(p0[0], p0[1]);
            Ph[tt][1] = pack2_hi_trunc(p0[2], p0[3]);
            Ph[tt][2] = pack2_hi_trunc(p1[0], p1[1]);
            Ph[tt][3] = pack2_hi_trunc(p1[2], p1[3]);
            Pl[tt][0] = pack2_lo_trunc(p0[0], p0[1]);
            Pl[tt][1] = pack2_lo_trunc(p0[2], p0[3]);
            Pl[tt][2] = pack2_lo_trunc(p1[0], p1[1]);
            Pl[tt][3] = pack2_lo_trunc(p1[2], p1[3]);
        }

        // ---- O += P . V ----
#pragma unroll
        for (int tt = 0; tt < 4; tt++) {
#pragma unroll
            for (int g = 0; g < 4; g++) {
                const int row = (tt << 4) + (lane & 15);
                const int ch  = (g << 1) + (lane >> 4);
                const uint32_t va = kb + AS_VHI + swz(row, ch);
                uint32_t vh[4], vl[4];
                LDM4_T(vh, va);
                LDM4_T(vl, va + 8192);
                MMA_BF16(O[2 * g],     Ph[tt], vh[0], vh[1]);
                MMA_BF16(O[2 * g],     Ph[tt], vl[0], vl[1]);
                MMA_BF16(O[2 * g],     Pl[tt], vh[0], vh[1]);
                MMA_BF16(O[2 * g + 1], Ph[tt], vh[2], vh[3]);
                MMA_BF16(O[2 * g + 1], Ph[tt], vl[2], vl[3]);
                MMA_BF16(O[2 * g + 1], Pl[tt], vh[2], vh[3]);
            }
        }

        // ---- pipeline advance ----
        if (kt < 30) {
            __syncthreads();
            issue_stage(kt + 2, kt & 1);
            CP_COMMIT;
            CP_WAIT1;
            __syncthreads();
        } else if (kt == 30) {
            CP_WAIT0;
            __syncthreads();
        }
    }

    // ---- normalize + write context as bf16 hi/lo planes [B,S,H*DK] ----
    const float i0 = 1.0f / l0;
    const float i1 = 1.0f / l1;
    const size_t co0 = (bS + qr) * D_MODEL + hoff + kc;
    const size_t co1 = co0 + (size_t)8 * D_MODEL;
#pragma unroll
    for (int j = 0; j < 8; j++) {
        const float v0 = O[j][0] * i0, v1 = O[j][1] * i0;
        const float v2 = O[j][2] * i1, v3 = O[j][3] * i1;
        *(uint32_t*)(g_Ch + co0 + (j << 3)) = pack2_hi_trunc(v0, v1);
        *(uint32_t*)(g_Cl + co0 + (j << 3)) = pack2_lo_trunc(v0, v1);
        *(uint32_t*)(g_Ch + co1 + (j << 3)) = pack2_hi_trunc(v2, v3);
        *(uint32_t*)(g_Cl + co1 + (j << 3)) = pack2_lo_trunc(v2, v3);
    }
}

// ---------------------------------------------------------------------------
extern "C" void kernel_launch(void* const* d_in, const int* in_sizes, int n_in,
                              void* d_out, int out_size)
{
    const float* q    = (const float*)d_in[0];
    const float* k    = (const float*)d_in[1];
    const float* v    = (const float*)d_in[2];
    const int*   mask = (const int*)  d_in[3];
    const float* wq   = (const float*)d_in[4];
    const float* bq   = (const float*)d_in[5];
    const float* wk   = (const float*)d_in[6];
    const float* bk   = (const float*)d_in[7];
    const float* wv   = (const float*)d_in[8];
    const float* bv   = (const float*)d_in[9];
    const float* wo   = (const float*)d_in[10];
    const float* bo   = (const float*)d_in[11];
    float* out = (float*)d_out;

    cudaFuncSetAttribute(gemm_qkv_kernel,
                         cudaFuncAttributeMaxDynamicSharedMemorySize, GEMM_SMEM);
    cudaFuncSetAttribute(gemm_out_kernel,
                         cudaFuncAttributeMaxDynamicSharedMemorySize, GEMM_SMEM);
    cudaFuncSetAttribute(attn_mma_kernel,
                         cudaFuncAttributeMaxDynamicSharedMemorySize, ATT_SMEM);

    mask8_kernel<<<(SEQ * SEQ) / (256 * 4), 256>>>(mask);
    split_qkv_kernel<<<dim3(NXE / 1024, 1, 3), 256>>>(q, k, v);
    split_w_kernel<<<dim3(NWE / 1024, 1, 4), 256>>>(wq, wk, wv, wo);

    gemm_qkv_kernel<<<dim3(8, 32, 3), 256, GEMM_SMEM>>>(bq, bk, bv);

    attn_mma_kernel<<<dim3(SEQ / 128, NHEAD, BATCH), 256, ATT_SMEM>>>();

    gemm_out_kernel<<<dim3(8, 32, 1), 256, GEMM_SMEM>>>(bo, out);
}

// round 8
// speedup vs baseline: 3.3095x; 1.0089x over previous
#include <cuda_runtime.h>
#include <cuda_bf16.h>
#include <cstdint>
#include <cstddef>

#define D_MODEL 1024
#define NHEAD   16
#define DK      64
#define BATCH   2
#define SEQ     2048
#define M_TOT   (BATCH * SEQ)                 // 4096
#define NXE     ((size_t)M_TOT * D_MODEL)     // 4M elems
#define NWE     ((size_t)D_MODEL * D_MODEL)   // 1M elems
#define LOG2E   1.4426950408889634f

// Scratch (allocation-free: __device__ globals)
__device__ __nv_bfloat16 g_INh[3 * NXE];   // split q,k,v inputs (hi)
__device__ __nv_bfloat16 g_INl[3 * NXE];   // (lo)
__device__ __nv_bfloat16 g_Wh[4 * NWE];    // split wq,wk,wv,wo (hi)
__device__ __nv_bfloat16 g_Wl[4 * NWE];    // (lo)
__device__ __nv_bfloat16 g_Ph[3 * NXE];    // projected Q,K,V (hi)
__device__ __nv_bfloat16 g_Pl[3 * NXE];    // (lo)
__device__ __nv_bfloat16 g_Ch[NXE];        // attention context (hi)
__device__ __nv_bfloat16 g_Cl[NXE];        // (lo)
__device__ unsigned char g_mask8[(size_t)SEQ * SEQ];

// ===========================================================================
// Helpers (baseline PTX ISA only — compute_103-safe)
// ===========================================================================
__device__ __forceinline__ uint32_t smem_u32(const void* p) {
    uint32_t a;
    asm("{ .reg .u64 t; cvta.to.shared.u64 t, %1; cvt.u32.u64 %0, t; }"
        : "=r"(a) : "l"(p));
    return a;
}

__device__ __forceinline__ float ex2f(float x) {
    float y;
    asm("ex2.approx.f32 %0, %1;" : "=f"(y) : "f"(x));
    return y;
}

#define LDM4(r, addr) \
    asm volatile("ldmatrix.sync.aligned.m8n8.x4.shared.b16 {%0,%1,%2,%3}, [%4];" \
        : "=r"((r)[0]), "=r"((r)[1]), "=r"((r)[2]), "=r"((r)[3]) : "r"(addr))

#define LDM4_T(r, addr) \
    asm volatile("ldmatrix.sync.aligned.m8n8.x4.trans.shared.b16 {%0,%1,%2,%3}, [%4];" \
        : "=r"((r)[0]), "=r"((r)[1]), "=r"((r)[2]), "=r"((r)[3]) : "r"(addr))

#define MMA_BF16(d, a, b0, b1) \
    asm volatile("mma.sync.aligned.m16n8k16.row.col.f32.bf16.bf16.f32 " \
        "{%0,%1,%2,%3}, {%4,%5,%6,%7}, {%8,%9}, {%0,%1,%2,%3};" \
        : "+f"((d)[0]), "+f"((d)[1]), "+f"((d)[2]), "+f"((d)[3]) \
        : "r"((a)[0]), "r"((a)[1]), "r"((a)[2]), "r"((a)[3]), "r"(b0), "r"(b1))

#define CP16(sa, gp) \
    asm volatile("{ .reg .u64 g; cvta.to.global.u64 g, %1; " \
                 "cp.async.cg.shared.global [%0], [g], 16; }" \
        :: "r"((uint32_t)(sa)), "l"(gp) : "memory")
#define CP_COMMIT  asm volatile("cp.async.commit_group;" ::: "memory")
#define CP_WAIT1   asm volatile("cp.async.wait_group 1;" ::: "memory")
#define CP_WAIT0   asm volatile("cp.async.wait_group 0;" ::: "memory")

__device__ __forceinline__ uint32_t pack_bf16(float a, float b) {
    __nv_bfloat162 h = __floats2bfloat162_rn(a, b);
    return *(uint32_t*)&h;
}
// Truncation split: hi = top 16 bits of fp32, lo = exact residual rounded.
__device__ __forceinline__ uint32_t pack2_hi_trunc(float a, float b) {
    return __byte_perm(__float_as_uint(a), __float_as_uint(b), 0x7632);
}
__device__ __forceinline__ uint32_t pack2_lo_trunc(float a, float b) {
    float ah = __uint_as_float(__float_as_uint(a) & 0xFFFF0000u);
    float bh = __uint_as_float(__float_as_uint(b) & 0xFFFF0000u);
    return pack_bf16(a - ah, b - bh);
}
__device__ __forceinline__ void cvt4_split(float4 f, uint2& hi, uint2& lo) {
    hi.x = pack2_hi_trunc(f.x, f.y);  hi.y = pack2_hi_trunc(f.z, f.w);
    lo.x = pack2_lo_trunc(f.x, f.y);  lo.y = pack2_lo_trunc(f.z, f.w);
}

// XOR swizzle: 128B rows, 16B chunks permuted within row (ldmatrix-safe)
__device__ __forceinline__ uint32_t swz(uint32_t row, uint32_t chunk) {
    return (row << 7) + ((chunk ^ (row & 7)) << 4);
}

// ===========================================================================
// Pre-pass kernels
// ===========================================================================
__global__ void mask8_kernel(const int* __restrict__ m)
{
    const size_t i = ((size_t)blockIdx.x * 256 + threadIdx.x) << 2;
    int4 v = *(const int4*)(m + i);
    uchar4 o;
    o.x = (unsigned char)v.x; o.y = (unsigned char)v.y;
    o.z = (unsigned char)v.z; o.w = (unsigned char)v.w;
    *(uchar4*)(g_mask8 + i) = o;
}

// One launch splits q,k,v (3 x 4096 blocks) and wq,wk,wv,wo (4 x 1024 blocks).
__global__ void split_all_kernel(
    const float* __restrict__ q,  const float* __restrict__ k,
    const float* __restrict__ v,
    const float* __restrict__ w0, const float* __restrict__ w1,
    const float* __restrict__ w2, const float* __restrict__ w3)
{
    const int blk = blockIdx.x;
    const float* src;
    __nv_bfloat16 *dh, *dl;
    size_t i;
    if (blk < 12288) {                       // inputs: 3 x 4096 blocks
        const int z = blk >> 12;
        src = (z == 0) ? q : (z == 1) ? k : v;
        i = ((size_t)(blk & 4095) * 256 + threadIdx.x) << 2;
        dh = g_INh + (size_t)z * NXE;
        dl = g_INl + (size_t)z * NXE;
    } else {                                 // weights: 4 x 1024 blocks
        const int wblk = blk - 12288;
        const int z = wblk >> 10;
        src = (z == 0) ? w0 : (z == 1) ? w1 : (z == 2) ? w2 : w3;
        i = ((size_t)(wblk & 1023) * 256 + threadIdx.x) << 2;
        dh = g_Wh + (size_t)z * NWE;
        dl = g_Wl + (size_t)z * NWE;
    }
    float4 f = *(const float4*)(src + i);
    uint2 hi, lo; cvt4_split(f, hi, lo);
    *(uint2*)(dh + i) = hi;
    *(uint2*)(dl + i) = lo;
}

// ===========================================================================
// GEMM core (pre-split bf16 operands, cp.async 3-stage pipeline)
// CTA tile 128x128, BK=32. smem stage 32K: A(hi|lo packed rows) 16K + B 16K.
// ===========================================================================
#define GSTG      32768
#define GEMM_SMEM (3 * GSTG)   // 98304

__device__ __forceinline__ void gemm_core(
    const __nv_bfloat16* __restrict__ Xh, const __nv_bfloat16* __restrict__ Xl,
    const __nv_bfloat16* __restrict__ Wh, const __nv_bfloat16* __restrict__ Wl,
    uint32_t sb, int m0, int n0, float (&acc)[4][4][4])
{
    const int t    = threadIdx.x;
    const int lane = t & 31;
    const int wid  = t >> 5;
    const int wm   = (wid & 1) << 6;
    const int wn   = (wid >> 1) << 5;

    auto issue = [&](int kt, int s) {
        const uint32_t base = sb + s * GSTG;
        const int k0 = kt << 5;
#pragma unroll
        for (int i = 0; i < 4; i++) {
            const int idx = t + (i << 8);
            const int row = idx >> 3, ch = idx & 7;
            const __nv_bfloat16* px = (ch < 4) ? Xh : Xl;
            const __nv_bfloat16* pw = (ch < 4) ? Wh : Wl;
            const int cc = (ch & 3) << 3;
            const uint32_t so = swz(row, ch);
            CP16(base + so,         px + (size_t)(m0 + row) * D_MODEL + k0 + cc);
            CP16(base + 16384 + so, pw + (size_t)(n0 + row) * D_MODEL + k0 + cc);
        }
    };

    issue(0, 0); CP_COMMIT;
    issue(1, 1); CP_COMMIT;

    for (int kt = 0; kt < 32; kt++) {
        if (kt < 30) { CP_WAIT1; } else { CP_WAIT0; }
        __syncthreads();
        if (kt < 30) { issue(kt + 2, (kt + 2) % 3); CP_COMMIT; }

        const uint32_t abuf = sb + (kt % 3) * GSTG;
        const uint32_t bbuf = abuf + 16384;
#pragma unroll
        for (int ks = 0; ks < 2; ks++) {
            uint32_t bh[4][2], bl[4][2];
#pragma unroll
            for (int p = 0; p < 2; p++) {
                const int nr = wn + (p << 4) + (lane & 7) + ((lane >> 4) << 3);
                const int ch = (ks << 1) + ((lane >> 3) & 1);
                uint32_t qq[4];
                LDM4(qq, bbuf + swz(nr, ch));
                bh[2 * p][0] = qq[0]; bh[2 * p][1] = qq[1];
                bh[2 * p + 1][0] = qq[2]; bh[2 * p + 1][1] = qq[3];
                LDM4(qq, bbuf + swz(nr, ch + 4));
                bl[2 * p][0] = qq[0]; bl[2 * p][1] = qq[1];
                bl[2 * p + 1][0] = qq[2]; bl[2 * p + 1][1] = qq[3];
            }
#pragma unroll
            for (int mi = 0; mi < 4; mi++) {
                const int row = wm + (mi << 4) + (lane & 15);
                const int ch  = (ks << 1) + (lane >> 4);
                uint32_t ah[4], al[4];
                LDM4(ah, abuf + swz(row, ch));
                LDM4(al, abuf + swz(row, ch + 4));
#pragma unroll
                for (int ni = 0; ni < 4; ni++) {
                    MMA_BF16(acc[mi][ni], ah, bh[ni][0], bh[ni][1]);
                    MMA_BF16(acc[mi][ni], ah, bl[ni][0], bl[ni][1]);
                    MMA_BF16(acc[mi][ni], al, bh[ni][0], bh[ni][1]);
                }
            }
        }
    }
}

// ---- batched Q/K/V projections. Q (z==0) pre-scaled by 0.125*log2(e) so
//      attention scores land directly in the exp2 domain. ----
__global__ __launch_bounds__(256, 2) void gemm_qkv_kernel(
    const float* __restrict__ bq, const float* __restrict__ bk,
    const float* __restrict__ bv)
{
    extern __shared__ char sm[];
    const uint32_t sb = smem_u32(sm);
    const int z  = blockIdx.z;
    const int m0 = blockIdx.y << 7;
    const int n0 = blockIdx.x << 7;
    const size_t zo = (size_t)z * NXE;

    float acc[4][4][4] = {};
    gemm_core(g_INh + zo, g_INl + zo,
              g_Wh + (size_t)z * NWE, g_Wl + (size_t)z * NWE,
              sb, m0, n0, acc);

    const float* bias = (z == 0) ? bq : (z == 1) ? bk : bv;
    const float sc = (z == 0) ? (0.125f * LOG2E) : 1.0f;
    __nv_bfloat16* Yh = g_Ph + zo;
    __nv_bfloat16* Yl = g_Pl + zo;

    const int lane = threadIdx.x & 31;
    const int wid  = threadIdx.x >> 5;
    const int wm   = (wid & 1) << 6;
    const int wn   = (wid >> 1) << 5;
    const int lr4  = lane >> 2;
    const int lc2  = (lane & 3) << 1;
#pragma unroll
    for (int mi = 0; mi < 4; mi++) {
        const int r = m0 + wm + (mi << 4) + lr4;
#pragma unroll
        for (int ni = 0; ni < 4; ni++) {
            const int c = n0 + wn + (ni << 3) + lc2;
            const float bx = bias[c], by = bias[c + 1];
            const float v0 = (acc[mi][ni][0] + bx) * sc, v1 = (acc[mi][ni][1] + by) * sc;
            const float v2 = (acc[mi][ni][2] + bx) * sc, v3 = (acc[mi][ni][3] + by) * sc;
            *(uint32_t*)(Yh + (size_t)r * D_MODEL + c)       = pack2_hi_trunc(v0, v1);
            *(uint32_t*)(Yl + (size_t)r * D_MODEL + c)       = pack2_lo_trunc(v0, v1);
            *(uint32_t*)(Yh + (size_t)(r + 8) * D_MODEL + c) = pack2_hi_trunc(v2, v3);
            *(uint32_t*)(Yl + (size_t)(r + 8) * D_MODEL + c) = pack2_lo_trunc(v2, v3);
        }
    }
}

// ---- output projection, fp32 epilogue ----
__global__ __launch_bounds__(256, 2) void gemm_out_kernel(
    const float* __restrict__ bo, float* __restrict__ out)
{
    extern __shared__ char sm[];
    const uint32_t sb = smem_u32(sm);
    const int m0 = blockIdx.y << 7;
    const int n0 = blockIdx.x << 7;

    float acc[4][4][4] = {};
    gemm_core(g_Ch, g_Cl, g_Wh + 3 * NWE, g_Wl + 3 * NWE, sb, m0, n0, acc);

    const int lane = threadIdx.x & 31;
    const int wid  = threadIdx.x >> 5;
    const int wm   = (wid & 1) << 6;
    const int wn   = (wid >> 1) << 5;
    const int lr4  = lane >> 2;
    const int lc2  = (lane & 3) << 1;
#pragma unroll
    for (int mi = 0; mi < 4; mi++) {
        const int r = m0 + wm + (mi << 4) + lr4;
#pragma unroll
        for (int ni = 0; ni < 4; ni++) {
            const int c = n0 + wn + (ni << 3) + lc2;
            const float bx = bo[c], by = bo[c + 1];
            float2 o0, o1;
            o0.x = acc[mi][ni][0] + bx; o0.y = acc[mi][ni][1] + by;
            o1.x = acc[mi][ni][2] + bx; o1.y = acc[mi][ni][3] + by;
            *(float2*)(out + (size_t)r * D_MODEL + c)       = o0;
            *(float2*)(out + (size_t)(r + 8) * D_MODEL + c) = o1;
        }
    }
}

// ===========================================================================
// Tensor-core flash attention: scores arrive in exp2 domain (Q pre-scaled by
// 0.125*log2e). Masked score -> -log2e. ONE __syncthreads per k-tile:
//   {work(kt)} ; cp.async.wait_group 0 ; __syncthreads ; issue(kt+2)
// The single barrier proves both (a) all warps done reading buf kt&1 and
// (b) everyone's stage-(kt+1) copies landed.
// smem: Qh 16K | Ql 16K | 2 x stage(Kh 8K, Kl 8K, Vh 8K, Vl 8K) = 96 KB
// ===========================================================================
#define AS_QLO   16384
#define AS_STG   32768
#define AS_STGSZ 32768
#define AS_KLO   8192
#define AS_VHI   16384
#define AS_VLO   24576
#define ATT_SMEM 98304

__global__ __launch_bounds__(256, 2) void attn_mma_kernel()
{
    extern __shared__ char sm[];
    const uint32_t sb = smem_u32(sm);
    const int t    = threadIdx.x;
    const int lane = t & 31;
    const int w    = t >> 5;
    const int b  = blockIdx.z;
    const int h  = blockIdx.y;
    const int q0 = blockIdx.x << 7;
    const size_t bS   = (size_t)b * SEQ;
    const size_t hoff = (size_t)h * DK;

    const __nv_bfloat16* Qh = g_Ph;
    const __nv_bfloat16* Ql = g_Pl;
    const __nv_bfloat16* Kh = g_Ph + NXE;
    const __nv_bfloat16* Kl = g_Pl + NXE;
    const __nv_bfloat16* Vh = g_Ph + 2 * NXE;
    const __nv_bfloat16* Vl = g_Pl + 2 * NXE;

    auto issue_stage = [&](int kt, int bufsel) {
        const uint32_t base = sb + AS_STG + bufsel * AS_STGSZ;
#pragma unroll
        for (int i = 0; i < 2; i++) {
            const int idx = t + (i << 8);
            const int row = idx >> 3, ch = idx & 7;
            const size_t go = (bS + (kt << 6) + row) * D_MODEL + hoff + (ch << 3);
            const uint32_t so = swz(row, ch);
            CP16(base + so,          Kh + go);
            CP16(base + AS_KLO + so, Kl + go);
            CP16(base + AS_VHI + so, Vh + go);
            CP16(base + AS_VLO + so, Vl + go);
        }
    };

    // prologue: group A = Q + stage0, group B = stage1
#pragma unroll
    for (int i = 0; i < 4; i++) {
        const int idx = t + (i << 8);
        const int row = idx >> 3, ch = idx & 7;
        const size_t go = (bS + q0 + row) * D_MODEL + hoff + (ch << 3);
        const uint32_t so = swz(row, ch);
        CP16(sb + so,          Qh + go);
        CP16(sb + AS_QLO + so, Ql + go);
    }
    issue_stage(0, 0);
    CP_COMMIT;
    issue_stage(1, 1);
    CP_COMMIT;
    CP_WAIT1;           // group A (Q + stage0) landed
    __syncthreads();

    float O[8][4] = {};
    float m0 = -1e30f, m1 = -1e30f, l0 = 0.0f, l1 = 0.0f;

    const int qr = q0 + (w << 4) + (lane >> 2);
    const int kc = (lane & 3) << 1;

    for (int kt = 0; kt < SEQ / 64; kt++) {
        const uint32_t kb = sb + AS_STG + (kt & 1) * AS_STGSZ;

        // ---- mask prefetch (latency hidden behind the QK MMAs) ----
        const unsigned char* mp0 = g_mask8 + (size_t)qr * SEQ + (kt << 6) + kc;
        const unsigned char* mp1 = mp0 + (size_t)8 * SEQ;
        unsigned short mk0[8], mk1[8];
#pragma unroll
        for (int j = 0; j < 8; j++) {
            mk0[j] = *(const unsigned short*)(mp0 + (j << 3));
            mk1[j] = *(const unsigned short*)(mp1 + (j << 3));
        }

        // ---- S = Q . K^T  (already in exp2 domain) ----
        float S[8][4] = {};
#pragma unroll
        for (int ks = 0; ks < 4; ks++) {
            uint32_t qh[4], ql[4];
            {
                const int row = (w << 4) + (lane & 15);
                const int ch  = (ks << 1) + (lane >> 4);
                const uint32_t qa = sb + swz(row, ch);
                LDM4(qh, qa);
                LDM4(ql, qa + AS_QLO);
            }
#pragma unroll
            for (int g = 0; g < 4; g++) {
                const int nr = (g << 4) + (lane & 7) + ((lane >> 4) << 3);
                const int ch = (ks << 1) + ((lane >> 3) & 1);
                const uint32_t ka = kb + swz(nr, ch);
                uint32_t kh[4], kl[4];
                LDM4(kh, ka);
                LDM4(kl, ka + AS_KLO);
                MMA_BF16(S[2 * g],     qh, kh[0], kh[1]);
                MMA_BF16(S[2 * g],     qh, kl[0], kl[1]);
                MMA_BF16(S[2 * g],     ql, kh[0], kh[1]);
                MMA_BF16(S[2 * g + 1], qh, kh[2], kh[3]);
                MMA_BF16(S[2 * g + 1], qh, kl[2], kl[3]);
                MMA_BF16(S[2 * g + 1], ql, kh[2], kh[3]);
            }
        }

        // ---- soft mask: masked -> -log2(e)  (== -1 in natural domain) ----
#pragma unroll
        for (int j = 0; j < 8; j++) {
            S[j][0] = (mk0[j] & 0xff) ? S[j][0] : -LOG2E;
            S[j][1] = (mk0[j] >> 8)   ? S[j][1] : -LOG2E;
            S[j][2] = (mk1[j] & 0xff) ? S[j][2] : -LOG2E;
            S[j][3] = (mk1[j] >> 8)   ? S[j][3] : -LOG2E;
        }

        // ---- online softmax in exp2 domain ----
        float tm0 = -1e30f, tm1 = -1e30f;
#pragma unroll
        for (int j = 0; j < 8; j++) {
            tm0 = fmaxf(tm0, fmaxf(S[j][0], S[j][1]));
            tm1 = fmaxf(tm1, fmaxf(S[j][2], S[j][3]));
        }
        tm0 = fmaxf(tm0, __shfl_xor_sync(0xffffffffu, tm0, 1));
        tm0 = fmaxf(tm0, __shfl_xor_sync(0xffffffffu, tm0, 2));
        tm1 = fmaxf(tm1, __shfl_xor_sync(0xffffffffu, tm1, 1));
        tm1 = fmaxf(tm1, __shfl_xor_sync(0xffffffffu, tm1, 2));
        const float mn0 = fmaxf(m0, tm0);
        const float mn1 = fmaxf(m1, tm1);
        const float a0 = ex2f(m0 - mn0);
        const float a1 = ex2f(m1 - mn1);
        float rs0 = 0.0f, rs1 = 0.0f;
#pragma unroll
        for (int j = 0; j < 8; j++) {
            S[j][0] = ex2f(S[j][0] - mn0);
            S[j][1] = ex2f(S[j][1] - mn0);
            S[j][2] = ex2f(S[j][2] - mn1);
            S[j][3] = ex2f(S[j][3] - mn1);
            rs0 += S[j][0] + S[j][1];
            rs1 += S[j][2] + S[j][3];
        }
        rs0 += __shfl_xor_sync(0xffffffffu, rs0, 1);
        rs0 += __shfl_xor_sync(0xffffffffu, rs0, 2);
        rs1 += __shfl_xor_sync(0xffffffffu, rs1, 1);
        rs1 += __shfl_xor_sync(0xffffffffu, rs1, 2);
        l0 = l0 * a0 + rs0;
        l1 = l1 * a1 + rs1;
        m0 = mn0; m1 = mn1;
#pragma unroll
        for (int j = 0; j < 8; j++) {
            O[j][0] *= a0; O[j][1] *= a0;
            O[j][2] *= a1; O[j][3] *= a1;
        }

        // ---- re-pack P into bf16 hi/lo A-frags (truncation split) ----
        uint32_t Ph[4][4], Pl[4][4];
#pragma unroll
        for (int tt = 0; tt < 4; tt++) {
            const float* p0 = S[2 * tt];
            const float* p1 = S[2 * tt + 1];
            Ph[tt][0] = pack2_hi_trunc(p0[0], p0[1]);
            Ph[tt][1] = pack2_hi_trunc(p0[2], p0[3]);
            Ph[tt][2] = pack2_hi_trunc(p1[0], p1[1]);
            Ph[tt][3] = pack2_hi_trunc(p1[2], p1[3]);
            Pl[tt][0] = pack2_lo_trunc(p0[0], p0[1]);
            Pl[tt][1] = pack2_lo_trunc(p0[2], p0[3]);
            Pl[tt][2] = pack2_lo_trunc(p1[0], p1[1]);
            Pl[tt][3] = pack2_lo_trunc(p1[2], p1[3]);
        }

        // ---- O += P . V ----
#pragma unroll
        for (int tt = 0; tt < 4; tt++) {
#pragma unroll
            for (int g = 0; g < 4; g++) {
                const int row = (tt << 4) + (lane & 15);
                const int ch  = (g << 1) + (lane >> 4);
                const uint32_t va = kb + AS_VHI + swz(row, ch);
                uint32_t vh[4], vl[4];
                LDM4_T(vh, va);
                LDM4_T(vl, va + 8192);
                MMA_BF16(O[2 * g],     Ph[tt], vh[0], vh[1]);
                MMA_BF16(O[2 * g],     Ph[tt], vl[0], vl[1]);
                MMA_BF16(O[2 * g],     Pl[tt], vh[0], vh[1]);
                MMA_BF16(O[2 * g + 1], Ph[tt], vh[2], vh[3]);
                MMA_BF16(O[2 * g + 1], Ph[tt], vl[2], vl[3]);
                MMA_BF16(O[2 * g + 1], Pl[tt], vh[2], vh[3]);
            }
        }

        // ---- pipeline advance: ONE barrier per kt ----
        if (kt < 31) {
            CP_WAIT0;                        // stage kt+1 (own copies) landed
            __syncthreads();                 // all reads of buf kt&1 done AND
                                             // all warps' kt+1 copies visible
            if (kt < 30) {
                issue_stage(kt + 2, kt & 1); // overwrite just-freed buffer
                CP_COMMIT;
            }
        }
    }

    // ---- normalize + write context as bf16 hi/lo planes [B,S,H*DK] ----
    const float i0 = 1.0f / l0;
    const float i1 = 1.0f / l1;
    const size_t co0 = (bS + qr) * D_MODEL + hoff + kc;
    const size_t co1 = co0 + (size_t)8 * D_MODEL;
#pragma unroll
    for (int j = 0; j < 8; j++) {
        const float v0 = O[j][0] * i0, v1 = O[j][1] * i0;
        const float v2 = O[j][2] * i1, v3 = O[j][3] * i1;
        *(uint32_t*)(g_Ch + co0 + (j << 3)) = pack2_hi_trunc(v0, v1);
        *(uint32_t*)(g_Cl + co0 + (j << 3)) = pack2_lo_trunc(v0, v1);
        *(uint32_t*)(g_Ch + co1 + (j << 3)) = pack2_hi_trunc(v2, v3);
        *(uint32_t*)(g_Cl + co1 + (j << 3)) = pack2_lo_trunc(v2, v3);
    }
}

// ---------------------------------------------------------------------------
extern "C" void kernel_launch(void* const* d_in, const int* in_sizes, int n_in,
                              void* d_out, int out_size)
{
    const float* q    = (const float*)d_in[0];
    const float* k    = (const float*)d_in[1];
    const float* v    = (const float*)d_in[2];
    const int*   mask = (const int*)  d_in[3];
    const float* wq   = (const float*)d_in[4];
    const float* bq   = (const float*)d_in[5];
    const float* wk   = (const float*)d_in[6];
    const float* bk   = (const float*)d_in[7];
    const float* wv   = (const float*)d_in[8];
    const float* bv   = (const float*)d_in[9];
    const float* wo   = (const float*)d_in[10];
    const float* bo   = (const float*)d_in[11];
    float* out = (float*)d_out;

    cudaFuncSetAttribute(gemm_qkv_kernel,
                         cudaFuncAttributeMaxDynamicSharedMemorySize, GEMM_SMEM);
    cudaFuncSetAttribute(gemm_out_kernel,
                         cudaFuncAttributeMaxDynamicSharedMemorySize, GEMM_SMEM);
    cudaFuncSetAttribute(attn_mma_kernel,
                         cudaFuncAttributeMaxDynamicSharedMemorySize, ATT_SMEM);

    // one merged split prepass: 3*4096 input blocks + 4*1024 weight blocks
    split_all_kernel<<<16384, 256>>>(q, k, v, wq, wk, wv, wo);

    gemm_qkv_kernel<<<dim3(8, 32, 3), 256, GEMM_SMEM>>>(bq, bk, bv);

    // mask prepass rides in gemm_qkv's ragged tail wave
    mask8_kernel<<<(SEQ * SEQ) / (256 * 4), 256>>>(mask);

    attn_mma_kernel<<<dim3(SEQ / 128, NHEAD, BATCH), 256, ATT_SMEM>>>();

    gemm_out_kernel<<<dim3(8, 32, 1), 256, GEMM_SMEM>>>(bo, out);
}

// round 9
// speedup vs baseline: 3.3658x; 1.0170x over previous
#include <cuda_runtime.h>
#include <cuda_bf16.h>
#include <cstdint>
#include <cstddef>

#define D_MODEL 1024
#define NHEAD   16
#define DK      64
#define BATCH   2
#define SEQ     2048
#define M_TOT   (BATCH * SEQ)                 // 4096
#define NXE     ((size_t)M_TOT * D_MODEL)     // 4M elems
#define NWE     ((size_t)D_MODEL * D_MODEL)   // 1M elems
#define LOG2E   1.4426950408889634f

// Scratch (allocation-free: __device__ globals)
__device__ __nv_bfloat16 g_INh[3 * NXE];   // split q,k,v inputs (hi)
__device__ __nv_bfloat16 g_INl[3 * NXE];   // (lo)
__device__ __nv_bfloat16 g_Wh[4 * NWE];    // split wq,wk,wv,wo (hi)
__device__ __nv_bfloat16 g_Wl[4 * NWE];    // (lo)
__device__ __nv_bfloat16 g_Ph[3 * NXE];    // projected Q,K,V (hi)
__device__ __nv_bfloat16 g_Pl[3 * NXE];    // (lo)
__device__ __nv_bfloat16 g_Ch[NXE];        // attention context (hi)
__device__ __nv_bfloat16 g_Cl[NXE];        // (lo)
__device__ uint64_t      g_maskb[(size_t)SEQ * SEQ / 64];  // bit-packed mask

// ===========================================================================
// Helpers (baseline PTX ISA only — compute_103-safe)
// ===========================================================================
__device__ __forceinline__ uint32_t smem_u32(const void* p) {
    uint32_t a;
    asm("{ .reg .u64 t; cvta.to.shared.u64 t, %1; cvt.u32.u64 %0, t; }"
        : "=r"(a) : "l"(p));
    return a;
}

__device__ __forceinline__ float ex2f(float x) {
    float y;
    asm("ex2.approx.f32 %0, %1;" : "=f"(y) : "f"(x));
    return y;
}

#define LDM4(r, addr) \
    asm volatile("ldmatrix.sync.aligned.m8n8.x4.shared.b16 {%0,%1,%2,%3}, [%4];" \
        : "=r"((r)[0]), "=r"((r)[1]), "=r"((r)[2]), "=r"((r)[3]) : "r"(addr))

#define LDM4_T(r, addr) \
    asm volatile("ldmatrix.sync.aligned.m8n8.x4.trans.shared.b16 {%0,%1,%2,%3}, [%4];" \
        : "=r"((r)[0]), "=r"((r)[1]), "=r"((r)[2]), "=r"((r)[3]) : "r"(addr))

#define MMA_BF16(d, a, b0, b1) \
    asm volatile("mma.sync.aligned.m16n8k16.row.col.f32.bf16.bf16.f32 " \
        "{%0,%1,%2,%3}, {%4,%5,%6,%7}, {%8,%9}, {%0,%1,%2,%3};" \
        : "+f"((d)[0]), "+f"((d)[1]), "+f"((d)[2]), "+f"((d)[3]) \
        : "r"((a)[0]), "r"((a)[1]), "r"((a)[2]), "r"((a)[3]), "r"(b0), "r"(b1))

#define CP16(sa, gp) \
    asm volatile("{ .reg .u64 g; cvta.to.global.u64 g, %1; " \
                 "cp.async.cg.shared.global [%0], [g], 16; }" \
        :: "r"((uint32_t)(sa)), "l"(gp) : "memory")
#define CP_COMMIT  asm volatile("cp.async.commit_group;" ::: "memory")
#define CP_WAIT1   asm volatile("cp.async.wait_group 1;" ::: "memory")
#define CP_WAIT0   asm volatile("cp.async.wait_group 0;" ::: "memory")

__device__ __forceinline__ uint32_t pack_bf16(float a, float b) {
    __nv_bfloat162 h = __floats2bfloat162_rn(a, b);
    return *(uint32_t*)&h;
}
// Truncation split: hi = top 16 bits of fp32, lo = exact residual rounded.
__device__ __forceinline__ uint32_t pack2_hi_trunc(float a, float b) {
    return __byte_perm(__float_as_uint(a), __float_as_uint(b), 0x7632);
}
__device__ __forceinline__ uint32_t pack2_lo_trunc(float a, float b) {
    float ah = __uint_as_float(__float_as_uint(a) & 0xFFFF0000u);
    float bh = __uint_as_float(__float_as_uint(b) & 0xFFFF0000u);
    return pack_bf16(a - ah, b - bh);
}
__device__ __forceinline__ void cvt4_split(float4 f, uint2& hi, uint2& lo) {
    hi.x = pack2_hi_trunc(f.x, f.y);  hi.y = pack2_hi_trunc(f.z, f.w);
    lo.x = pack2_lo_trunc(f.x, f.y);  lo.y = pack2_lo_trunc(f.z, f.w);
}

// XOR swizzle: 128B rows, 16B chunks permuted within row (ldmatrix-safe)
__device__ __forceinline__ uint32_t swz(uint32_t row, uint32_t chunk) {
    return (row << 7) + ((chunk ^ (row & 7)) << 4);
}

// ===========================================================================
// Pre-pass kernels
// ===========================================================================
// mask int32 -> 1 bit per element; row-major, bit index = col % 64 in u64 word
__global__ void maskbit_kernel(const int* __restrict__ m)
{
    const size_t tid  = (size_t)blockIdx.x * 256 + threadIdx.x;
    const size_t base = tid << 5;   // 32 consecutive ints
    uint32_t bits = 0;
#pragma unroll
    for (int i = 0; i < 8; i++) {
        int4 v = *(const int4*)(m + base + (i << 2));
        bits |= (v.x ? 1u : 0u) << (4 * i);
        bits |= (v.y ? 1u : 0u) << (4 * i + 1);
        bits |= (v.z ? 1u : 0u) << (4 * i + 2);
        bits |= (v.w ? 1u : 0u) << (4 * i + 3);
    }
    ((uint32_t*)g_maskb)[tid] = bits;
}

// One launch splits q,k,v (3 x 4096 blocks) and wq,wk,wv,wo (4 x 1024 blocks).
__global__ void split_all_kernel(
    const float* __restrict__ q,  const float* __restrict__ k,
    const float* __restrict__ v,
    const float* __restrict__ w0, const float* __restrict__ w1,
    const float* __restrict__ w2, const float* __restrict__ w3)
{
    const int blk = blockIdx.x;
    const float* src;
    __nv_bfloat16 *dh, *dl;
    size_t i;
    if (blk < 12288) {                       // inputs: 3 x 4096 blocks
        const int z = blk >> 12;
        src = (z == 0) ? q : (z == 1) ? k : v;
        i = ((size_t)(blk & 4095) * 256 + threadIdx.x) << 2;
        dh = g_INh + (size_t)z * NXE;
        dl = g_INl + (size_t)z * NXE;
    } else {                                 // weights: 4 x 1024 blocks
        const int wblk = blk - 12288;
        const int z = wblk >> 10;
        src = (z == 0) ? w0 : (z == 1) ? w1 : (z == 2) ? w2 : w3;
        i = ((size_t)(wblk & 1023) * 256 + threadIdx.x) << 2;
        dh = g_Wh + (size_t)z * NWE;
        dl = g_Wl + (size_t)z * NWE;
    }
    float4 f = *(const float4*)(src + i);
    uint2 hi, lo; cvt4_split(f, hi, lo);
    *(uint2*)(dh + i) = hi;
    *(uint2*)(dl + i) = lo;
}

// ===========================================================================
// GEMM core (pre-split bf16 operands, cp.async 3-stage pipeline)
// CTA tile 128x128, BK=32. smem stage 32K: A(hi|lo packed rows) 16K + B 16K.
// ===========================================================================
#define GSTG      32768
#define GEMM_SMEM (3 * GSTG)   // 98304

__device__ __forceinline__ void gemm_core(
    const __nv_bfloat16* __restrict__ Xh, const __nv_bfloat16* __restrict__ Xl,
    const __nv_bfloat16* __restrict__ Wh, const __nv_bfloat16* __restrict__ Wl,
    uint32_t sb, int m0, int n0, float (&acc)[4][4][4])
{
    const int t    = threadIdx.x;
    const int lane = t & 31;
    const int wid  = t >> 5;
    const int wm   = (wid & 1) << 6;
    const int wn   = (wid >> 1) << 5;

    auto issue = [&](int kt, int s) {
        const uint32_t base = sb + s * GSTG;
        const int k0 = kt << 5;
#pragma unroll
        for (int i = 0; i < 4; i++) {
            const int idx = t + (i << 8);
            const int row = idx >> 3, ch = idx & 7;
            const __nv_bfloat16* px = (ch < 4) ? Xh : Xl;
            const __nv_bfloat16* pw = (ch < 4) ? Wh : Wl;
            const int cc = (ch & 3) << 3;
            const uint32_t so = swz(row, ch);
            CP16(base + so,         px + (size_t)(m0 + row) * D_MODEL + k0 + cc);
            CP16(base + 16384 + so, pw + (size_t)(n0 + row) * D_MODEL + k0 + cc);
        }
    };

    issue(0, 0); CP_COMMIT;
    issue(1, 1); CP_COMMIT;

    for (int kt = 0; kt < 32; kt++) {
        if (kt < 30) { CP_WAIT1; } else { CP_WAIT0; }
        __syncthreads();
        if (kt < 30) { issue(kt + 2, (kt + 2) % 3); CP_COMMIT; }

        const uint32_t abuf = sb + (kt % 3) * GSTG;
        const uint32_t bbuf = abuf + 16384;
#pragma unroll
        for (int ks = 0; ks < 2; ks++) {
            uint32_t bh[4][2], bl[4][2];
#pragma unroll
            for (int p = 0; p < 2; p++) {
                const int nr = wn + (p << 4) + (lane & 7) + ((lane >> 4) << 3);
                const int ch = (ks << 1) + ((lane >> 3) & 1);
                uint32_t qq[4];
                LDM4(qq, bbuf + swz(nr, ch));
                bh[2 * p][0] = qq[0]; bh[2 * p][1] = qq[1];
                bh[2 * p + 1][0] = qq[2]; bh[2 * p + 1][1] = qq[3];
                LDM4(qq, bbuf + swz(nr, ch + 4));
                bl[2 * p][0] = qq[0]; bl[2 * p][1] = qq[1];
                bl[2 * p + 1][0] = qq[2]; bl[2 * p + 1][1] = qq[3];
            }
#pragma unroll
            for (int mi = 0; mi < 4; mi++) {
                const int row = wm + (mi << 4) + (lane & 15);
                const int ch  = (ks << 1) + (lane >> 4);
                uint32_t ah[4], al[4];
                LDM4(ah, abuf + swz(row, ch));
                LDM4(al, abuf + swz(row, ch + 4));
#pragma unroll
                for (int ni = 0; ni < 4; ni++) {
                    MMA_BF16(acc[mi][ni], ah, bh[ni][0], bh[ni][1]);
                    MMA_BF16(acc[mi][ni], ah, bl[ni][0], bl[ni][1]);
                    MMA_BF16(acc[mi][ni], al, bh[ni][0], bh[ni][1]);
                }
            }
        }
    }
}

// ---- batched Q/K/V projections. Q (z==0) pre-scaled by 0.125*log2(e) so
//      attention scores land directly in the exp2 domain. ----
__global__ __launch_bounds__(256, 2) void gemm_qkv_kernel(
    const float* __restrict__ bq, const float* __restrict__ bk,
    const float* __restrict__ bv)
{
    extern __shared__ char sm[];
    const uint32_t sb = smem_u32(sm);
    const int z  = blockIdx.z;
    const int m0 = blockIdx.y << 7;
    const int n0 = blockIdx.x << 7;
    const size_t zo = (size_t)z * NXE;

    float acc[4][4][4] = {};
    gemm_core(g_INh + zo, g_INl + zo,
              g_Wh + (size_t)z * NWE, g_Wl + (size_t)z * NWE,
              sb, m0, n0, acc);

    const float* bias = (z == 0) ? bq : (z == 1) ? bk : bv;
    const float sc = (z == 0) ? (0.125f * LOG2E) : 1.0f;
    __nv_bfloat16* Yh = g_Ph + zo;
    __nv_bfloat16* Yl = g_Pl + zo;

    const int lane = threadIdx.x & 31;
    const int wid  = threadIdx.x >> 5;
    const int wm   = (wid & 1) << 6;
    const int wn   = (wid >> 1) << 5;
    const int lr4  = lane >> 2;
    const int lc2  = (lane & 3) << 1;
#pragma unroll
    for (int mi = 0; mi < 4; mi++) {
        const int r = m0 + wm + (mi << 4) + lr4;
#pragma unroll
        for (int ni = 0; ni < 4; ni++) {
            const int c = n0 + wn + (ni << 3) + lc2;
            const float bx = bias[c], by = bias[c + 1];
            const float v0 = (acc[mi][ni][0] + bx) * sc, v1 = (acc[mi][ni][1] + by) * sc;
            const float v2 = (acc[mi][ni][2] + bx) * sc, v3 = (acc[mi][ni][3] + by) * sc;
            *(uint32_t*)(Yh + (size_t)r * D_MODEL + c)       = pack2_hi_trunc(v0, v1);
            *(uint32_t*)(Yl + (size_t)r * D_MODEL + c)       = pack2_lo_trunc(v0, v1);
            *(uint32_t*)(Yh + (size_t)(r + 8) * D_MODEL + c) = pack2_hi_trunc(v2, v3);
            *(uint32_t*)(Yl + (size_t)(r + 8) * D_MODEL + c) = pack2_lo_trunc(v2, v3);
        }
    }
}

// ---- output projection, fp32 epilogue ----
__global__ __launch_bounds__(256, 2) void gemm_out_kernel(
    const float* __restrict__ bo, float* __restrict__ out)
{
    extern __shared__ char sm[];
    const uint32_t sb = smem_u32(sm);
    const int m0 = blockIdx.y << 7;
    const int n0 = blockIdx.x << 7;

    float acc[4][4][4] = {};
    gemm_core(g_Ch, g_Cl, g_Wh + 3 * NWE, g_Wl + 3 * NWE, sb, m0, n0, acc);

    const int lane = threadIdx.x & 31;
    const int wid  = threadIdx.x >> 5;
    const int wm   = (wid & 1) << 6;
    const int wn   = (wid >> 1) << 5;
    const int lr4  = lane >> 2;
    const int lc2  = (lane & 3) << 1;
#pragma unroll
    for (int mi = 0; mi < 4; mi++) {
        const int r = m0 + wm + (mi << 4) + lr4;
#pragma unroll
        for (int ni = 0; ni < 4; ni++) {
            const int c = n0 + wn + (ni << 3) + lc2;
            const float bx = bo[c], by = bo[c + 1];
            float2 o0, o1;
            o0.x = acc[mi][ni][0] + bx; o0.y = acc[mi][ni][1] + by;
            o1.x = acc[mi][ni][2] + bx; o1.y = acc[mi][ni][3] + by;
            *(float2*)(out + (size_t)r * D_MODEL + c)       = o0;
            *(float2*)(out + (size_t)(r + 8) * D_MODEL + c) = o1;
        }
    }
}

// ===========================================================================
// Tensor-core flash attention v3: 256 q-rows per CTA, 8 warps x 32 rows.
// K/V fragments amortize over 2x MMA work (smem traffic per FLOP halved).
// Bit-packed mask (1 u64 per row per 64-key tile). exp2-domain softmax.
// smem: Qh 32K | Ql 32K | 2 x stage(Kh 8K, Kl 8K, Vh 8K, Vl 8K) = 128 KB
// ===========================================================================
#define AS_QLO   32768
#define AS_STG   65536
#define AS_STGSZ 32768
#define AS_KLO   8192
#define AS_VHI   16384
#define AS_VLO   24576
#define ATT_SMEM 131072

__global__ __launch_bounds__(256, 1) void attn_mma_kernel()
{
    extern __shared__ char sm[];
    const uint32_t sb = smem_u32(sm);
    const int t    = threadIdx.x;
    const int lane = t & 31;
    const int w    = t >> 5;
    const int b  = blockIdx.z;
    const int h  = blockIdx.y;
    const int q0 = blockIdx.x << 8;          // 256 q rows per CTA
    const size_t bS   = (size_t)b * SEQ;
    const size_t hoff = (size_t)h * DK;

    const __nv_bfloat16* Qh = g_Ph;
    const __nv_bfloat16* Ql = g_Pl;
    const __nv_bfloat16* Kh = g_Ph + NXE;
    const __nv_bfloat16* Kl = g_Pl + NXE;
    const __nv_bfloat16* Vh = g_Ph + 2 * NXE;
    const __nv_bfloat16* Vl = g_Pl + 2 * NXE;

    auto issue_stage = [&](int kt, int bufsel) {
        const uint32_t base = sb + AS_STG + bufsel * AS_STGSZ;
#pragma unroll
        for (int i = 0; i < 2; i++) {
            const int idx = t + (i << 8);
            const int row = idx >> 3, ch = idx & 7;
            const size_t go = (bS + (kt << 6) + row) * D_MODEL + hoff + (ch << 3);
            const uint32_t so = swz(row, ch);
            CP16(base + so,          Kh + go);
            CP16(base + AS_KLO + so, Kl + go);
            CP16(base + AS_VHI + so, Vh + go);
            CP16(base + AS_VLO + so, Vl + go);
        }
    };

    // prologue: Q tile (256 rows) + stage0 in group A, stage1 in group B
#pragma unroll
    for (int i = 0; i < 8; i++) {
        const int idx = t + (i << 8);
        const int row = idx >> 3, ch = idx & 7;
        const size_t go = (bS + q0 + row) * D_MODEL + hoff + (ch << 3);
        const uint32_t so = swz(row, ch);
        CP16(sb + so,          Qh + go);
        CP16(sb + AS_QLO + so, Ql + go);
    }
    issue_stage(0, 0);
    CP_COMMIT;
    issue_stage(1, 1);
    CP_COMMIT;
    CP_WAIT1;
    __syncthreads();

    float O[2][8][4] = {};
    float mm[4], ll[4];
#pragma unroll
    for (int i = 0; i < 4; i++) { mm[i] = -1e30f; ll[i] = 0.0f; }

    const int qr0 = q0 + (w << 5) + (lane >> 2);   // warp covers rows qr0..+24
    const int kc  = (lane & 3) << 1;

    for (int kt = 0; kt < SEQ / 64; kt++) {
        const uint32_t kb = sb + AS_STG + (kt & 1) * AS_STGSZ;

        // ---- mask prefetch: 4 u64 words (64 key-bits each) ----
        const uint64_t* Mb = g_maskb + (size_t)qr0 * (SEQ / 64) + kt;
        const uint64_t w0 = Mb[0];
        const uint64_t w1 = Mb[(size_t)8  * (SEQ / 64)];
        const uint64_t w2 = Mb[(size_t)16 * (SEQ / 64)];
        const uint64_t w3 = Mb[(size_t)24 * (SEQ / 64)];

        // ---- S = Q . K^T  (32 q rows x 64 keys per warp) ----
        float S[2][8][4] = {};
#pragma unroll
        for (int ks = 0; ks < 4; ks++) {
            uint32_t kh[4][4], kl[4][4];
#pragma unroll
            for (int g = 0; g < 4; g++) {
                const int nr = (g << 4) + (lane & 7) + ((lane >> 4) << 3);
                const int ch = (ks << 1) + ((lane >> 3) & 1);
                const uint32_t ka = kb + swz(nr, ch);
                LDM4(kh[g], ka);
                LDM4(kl[g], ka + AS_KLO);
            }
#pragma unroll
            for (int mi = 0; mi < 2; mi++) {
                uint32_t qh[4], ql[4];
                const int row = (w << 5) + (mi << 4) + (lane & 15);
                const int ch  = (ks << 1) + (lane >> 4);
                const uint32_t qa = sb + swz(row, ch);
                LDM4(qh, qa);
                LDM4(ql, qa + AS_QLO);
#pragma unroll
                for (int g = 0; g < 4; g++) {
                    MMA_BF16(S[mi][2 * g],     qh, kh[g][0], kh[g][1]);
                    MMA_BF16(S[mi][2 * g],     qh, kl[g][0], kl[g][1]);
                    MMA_BF16(S[mi][2 * g],     ql, kh[g][0], kh[g][1]);
                    MMA_BF16(S[mi][2 * g + 1], qh, kh[g][2], kh[g][3]);
                    MMA_BF16(S[mi][2 * g + 1], qh, kl[g][2], kl[g][3]);
                    MMA_BF16(S[mi][2 * g + 1], ql, kh[g][2], kh[g][3]);
                }
            }
        }

        // ---- soft mask from bits: masked -> -log2(e) ----
#pragma unroll
        for (int mi = 0; mi < 2; mi++) {
            const uint64_t wa = mi ? w2 : w0;
            const uint64_t wb = mi ? w3 : w1;
#pragma unroll
            for (int j = 0; j < 8; j++) {
                const uint32_t sa = (uint32_t)(wa >> (8 * j + kc));
                const uint32_t sbm = (uint32_t)(wb >> (8 * j + kc));
                S[mi][j][0] = (sa  & 1) ? S[mi][j][0] : -LOG2E;
                S[mi][j][1] = (sa  & 2) ? S[mi][j][1] : -LOG2E;
                S[mi][j][2] = (sbm & 1) ? S[mi][j][2] : -LOG2E;
                S[mi][j][3] = (sbm & 2) ? S[mi][j][3] : -LOG2E;
            }
        }

        // ---- online softmax (exp2 domain), rows qr0+16mi, qr0+16mi+8 ----
#pragma unroll
        for (int mi = 0; mi < 2; mi++) {
            float tm0 = -1e30f, tm1 = -1e30f;
#pragma unroll
            for (int j = 0; j < 8; j++) {
                tm0 = fmaxf(tm0, fmaxf(S[mi][j][0], S[mi][j][1]));
                tm1 = fmaxf(tm1, fmaxf(S[mi][j][2], S[mi][j][3]));
            }
            tm0 = fmaxf(tm0, __shfl_xor_sync(0xffffffffu, tm0, 1));
            tm0 = fmaxf(tm0, __shfl_xor_sync(0xffffffffu, tm0, 2));
            tm1 = fmaxf(tm1, __shfl_xor_sync(0xffffffffu, tm1, 1));
            tm1 = fmaxf(tm1, __shfl_xor_sync(0xffffffffu, tm1, 2));
            const float mn0 = fmaxf(mm[2 * mi],     tm0);
            const float mn1 = fmaxf(mm[2 * mi + 1], tm1);
            const float a0 = ex2f(mm[2 * mi]     - mn0);
            const float a1 = ex2f(mm[2 * mi + 1] - mn1);
            float rs0 = 0.0f, rs1 = 0.0f;
#pragma unroll
            for (int j = 0; j < 8; j++) {
                S[mi][j][0] = ex2f(S[mi][j][0] - mn0);
                S[mi][j][1] = ex2f(S[mi][j][1] - mn0);
                S[mi][j][2] = ex2f(S[mi][j][2] - mn1);
                S[mi][j][3] = ex2f(S[mi][j][3] - mn1);
                rs0 += S[mi][j][0] + S[mi][j][1];
                rs1 += S[mi][j][2] + S[mi][j][3];
            }
            rs0 += __shfl_xor_sync(0xffffffffu, rs0, 1);
            rs0 += __shfl_xor_sync(0xffffffffu, rs0, 2);
            rs1 += __shfl_xor_sync(0xffffffffu, rs1, 1);
            rs1 += __shfl_xor_sync(0xffffffffu, rs1, 2);
            ll[2 * mi]     = ll[2 * mi]     * a0 + rs0;
            ll[2 * mi + 1] = ll[2 * mi + 1] * a1 + rs1;
            mm[2 * mi]     = mn0;
            mm[2 * mi + 1] = mn1;
#pragma unroll
            for (int j = 0; j < 8; j++) {
                O[mi][j][0] *= a0; O[mi][j][1] *= a0;
                O[mi][j][2] *= a1; O[mi][j][3] *= a1;
            }
        }

        // ---- re-pack P into bf16 hi/lo A-frags (truncation split) ----
        uint32_t Pha[2][4][4], Pla[2][4][4];
#pragma unroll
        for (int mi = 0; mi < 2; mi++) {
#pragma unroll
            for (int tt = 0; tt < 4; tt++) {
                const float* p0 = S[mi][2 * tt];
                const float* p1 = S[mi][2 * tt + 1];
                Pha[mi][tt][0] = pack2_hi_trunc(p0[0], p0[1]);
                Pha[mi][tt][1] = pack2_hi_trunc(p0[2], p0[3]);
                Pha[mi][tt][2] = pack2_hi_trunc(p1[0], p1[1]);
                Pha[mi][tt][3] = pack2_hi_trunc(p1[2], p1[3]);
                Pla[mi][tt][0] = pack2_lo_trunc(p0[0], p0[1]);
                Pla[mi][tt][1] = pack2_lo_trunc(p0[2], p0[3]);
                Pla[mi][tt][2] = pack2_lo_trunc(p1[0], p1[1]);
                Pla[mi][tt][3] = pack2_lo_trunc(p1[2], p1[3]);
            }
        }

        // ---- O += P . V ----
#pragma unroll
        for (int tt = 0; tt < 4; tt++) {
#pragma unroll
            for (int g = 0; g < 4; g++) {
                const int row = (tt << 4) + (lane & 15);
                const int ch  = (g << 1) + (lane >> 4);
                const uint32_t va = kb + AS_VHI + swz(row, ch);
                uint32_t vh[4], vl[4];
                LDM4_T(vh, va);
                LDM4_T(vl, va + 8192);
#pragma unroll
                for (int mi = 0; mi < 2; mi++) {
                    MMA_BF16(O[mi][2 * g],     Pha[mi][tt], vh[0], vh[1]);
                    MMA_BF16(O[mi][2 * g],     Pha[mi][tt], vl[0], vl[1]);
                    MMA_BF16(O[mi][2 * g],     Pla[mi][tt], vh[0], vh[1]);
                    MMA_BF16(O[mi][2 * g + 1], Pha[mi][tt], vh[2], vh[3]);
                    MMA_BF16(O[mi][2 * g + 1], Pha[mi][tt], vl[2], vl[3]);
                    MMA_BF16(O[mi][2 * g + 1], Pla[mi][tt], vh[2], vh[3]);
                }
            }
        }

        // ---- pipeline advance: ONE barrier per kt ----
        if (kt < 31) {
            CP_WAIT0;
            __syncthreads();
            if (kt < 30) {
                issue_stage(kt + 2, kt & 1);
                CP_COMMIT;
            }
        }
    }

    // ---- normalize + write context as bf16 hi/lo planes [B,S,H*DK] ----
#pragma unroll
    for (int mi = 0; mi < 2; mi++) {
        const float i0 = 1.0f / ll[2 * mi];
        const float i1 = 1.0f / ll[2 * mi + 1];
        const size_t co0 = (bS + qr0 + (mi << 4)) * D_MODEL + hoff + kc;
        const size_t co1 = co0 + (size_t)8 * D_MODEL;
#pragma unroll
        for (int j = 0; j < 8; j++) {
            const float v0 = O[mi][j][0] * i0, v1 = O[mi][j][1] * i0;
            const float v2 = O[mi][j][2] * i1, v3 = O[mi][j][3] * i1;
            *(uint32_t*)(g_Ch + co0 + (j << 3)) = pack2_hi_trunc(v0, v1);
            *(uint32_t*)(g_Cl + co0 + (j << 3)) = pack2_lo_trunc(v0, v1);
            *(uint32_t*)(g_Ch + co1 + (j << 3)) = pack2_hi_trunc(v2, v3);
            *(uint32_t*)(g_Cl + co1 + (j << 3)) = pack2_lo_trunc(v2, v3);
        }
    }
}

// ---------------------------------------------------------------------------
extern "C" void kernel_launch(void* const* d_in, const int* in_sizes, int n_in,
                              void* d_out, int out_size)
{
    const float* q    = (const float*)d_in[0];
    const float* k    = (const float*)d_in[1];
    const float* v    = (const float*)d_in[2];
    const int*   mask = (const int*)  d_in[3];
    const float* wq   = (const float*)d_in[4];
    const float* bq   = (const float*)d_in[5];
    const float* wk   = (const float*)d_in[6];
    const float* bk   = (const float*)d_in[7];
    const float* wv   = (const float*)d_in[8];
    const float* bv   = (const float*)d_in[9];
    const float* wo   = (const float*)d_in[10];
    const float* bo   = (const float*)d_in[11];
    float* out = (float*)d_out;

    cudaFuncSetAttribute(gemm_qkv_kernel,
                         cudaFuncAttributeMaxDynamicSharedMemorySize, GEMM_SMEM);
    cudaFuncSetAttribute(gemm_out_kernel,
                         cudaFuncAttributeMaxDynamicSharedMemorySize, GEMM_SMEM);
    cudaFuncSetAttribute(attn_mma_kernel,
                         cudaFuncAttributeMaxDynamicSharedMemorySize, ATT_SMEM);

    // merged split prepass: 3*4096 input blocks + 4*1024 weight blocks
    split_all_kernel<<<16384, 256>>>(q, k, v, wq, wk, wv, wo);

    gemm_qkv_kernel<<<dim3(8, 32, 3), 256, GEMM_SMEM>>>(bq, bk, bv);

    // mask bit-pack rides in gemm_qkv's ragged tail wave
    maskbit_kernel<<<(SEQ * SEQ) / (32 * 256), 256>>>(mask);

    attn_mma_kernel<<<dim3(SEQ / 256, NHEAD, BATCH), 256, ATT_SMEM>>>();

    gemm_out_kernel<<<dim3(8, 32, 1), 256, GEMM_SMEM>>>(bo, out);
}